// round 1
// baseline (speedup 1.0000x reference)
#include <cuda_runtime.h>

#define N_NODES 4096
#define FIN     512
#define NHEADS  4
#define FDIM    64
#define HF      256   // NHEADS*FDIM

// ---------------- scratch (device globals; no allocations allowed) ----------
__device__ float g_XW[(size_t)N_NODES * HF];     // 4 MB
__device__ float g_f1[NHEADS * N_NODES];
__device__ float g_f2[NHEADS * N_NODES];
__device__ float g_fmax2[NHEADS];

// ---------------- kernel 1: XW = X @ W  (fp32 tiled GEMM) -------------------
// M=4096, N=256, K=512. BM=BN=64, BK=16, 256 threads, 4x4 per thread.
__global__ void __launch_bounds__(256) gemm_xw(const float* __restrict__ X,
                                               const float* __restrict__ W) {
    __shared__ float Xs[16][65];   // [k][m], padded to kill store conflicts
    __shared__ float Ws[16][64];   // [k][n]
    const int t   = threadIdx.x;
    const int bn0 = blockIdx.x * 64;
    const int bm0 = blockIdx.y * 64;
    const int rb  = (t >> 4) << 2;   // 0..60
    const int cb  = (t & 15) << 2;   // 0..60

    float acc[4][4];
#pragma unroll
    for (int i = 0; i < 4; i++)
#pragma unroll
        for (int j = 0; j < 4; j++) acc[i][j] = 0.f;

    for (int k0 = 0; k0 < FIN; k0 += 16) {
#pragma unroll
        for (int i = 0; i < 4; i++) {
            int e  = t + i * 256;            // 0..1023
            int ar = e >> 4, ac = e & 15;    // 64x16 tile of X
            Xs[ac][ar] = X[(size_t)(bm0 + ar) * FIN + k0 + ac];
            int br = e >> 6, bc = e & 63;    // 16x64 tile of W
            Ws[br][bc] = W[(size_t)(k0 + br) * HF + bn0 + bc];
        }
        __syncthreads();
#pragma unroll
        for (int k = 0; k < 16; k++) {
            float av[4], bv[4];
#pragma unroll
            for (int i = 0; i < 4; i++) av[i] = Xs[k][rb + i];
#pragma unroll
            for (int j = 0; j < 4; j++) bv[j] = Ws[k][cb + j];
#pragma unroll
            for (int i = 0; i < 4; i++)
#pragma unroll
                for (int j = 0; j < 4; j++) acc[i][j] += av[i] * bv[j];
        }
        __syncthreads();
    }
#pragma unroll
    for (int i = 0; i < 4; i++)
#pragma unroll
        for (int j = 0; j < 4; j++)
            g_XW[(size_t)(bm0 + rb + i) * HF + bn0 + cb + j] = acc[i][j];
}

// ---------------- kernel 2: f1[h,n], f2[h,n] --------------------------------
// one block per node n; 256 threads, thread t covers (h=t/64, f=t%64)
__global__ void __launch_bounds__(256) f_kernel(const float* __restrict__ a_src,
                                                const float* __restrict__ a_dst) {
    const int n = blockIdx.x, t = threadIdx.x;
    float xw = g_XW[(size_t)n * HF + t];
    float s1 = xw * a_src[t];
    float s2 = xw * a_dst[t];
#pragma unroll
    for (int o = 16; o > 0; o >>= 1) {
        s1 += __shfl_down_sync(0xffffffffu, s1, o);
        s2 += __shfl_down_sync(0xffffffffu, s2, o);
    }
    __shared__ float w1[8], w2[8];
    if ((t & 31) == 0) { w1[t >> 5] = s1; w2[t >> 5] = s2; }
    __syncthreads();
    if (t < NHEADS) {
        g_f1[t * N_NODES + n] = w1[2 * t] + w1[2 * t + 1];
        g_f2[t * N_NODES + n] = w2[2 * t] + w2[2 * t + 1];
    }
}

// ---------------- kernel 3: fmax2[h] = max_j f2[h,j] ------------------------
__global__ void __launch_bounds__(256) fmax_kernel() {
    const int h = blockIdx.x, t = threadIdx.x;
    float m = -3.0e38f;
    for (int j = t; j < N_NODES; j += 256) m = fmaxf(m, g_f2[h * N_NODES + j]);
#pragma unroll
    for (int o = 16; o > 0; o >>= 1)
        m = fmaxf(m, __shfl_down_sync(0xffffffffu, m, o));
    __shared__ float wm[8];
    if ((t & 31) == 0) wm[t >> 5] = m;
    __syncthreads();
    if (t == 0) {
        float r = wm[0];
#pragma unroll
        for (int w = 1; w < 8; w++) r = fmaxf(r, wm[w]);
        g_fmax2[h] = r;
    }
}

// ---------------- kernel 4: fused masked-softmax aggregation + ELU ----------
// Block handles Mi=8 rows x all 4096 j x all heads. Single pass:
//   m[h,i] = lrelu(f1[h,i] + max_j f2[h,j])  (analytic stabilizer, >= any score)
//   w      = A[i,j] ? exp(lrelu(f1+f2) - m) : 0
//   out    = elu( (sum_j w * XW[j]) / (sum_j w) )
#define MI 8
#define JC 32
__global__ void __launch_bounds__(256) agg_kernel(const int* __restrict__ A,
                                                  float* __restrict__ out) {
    __shared__ int   As[MI][JC];           // 1 KB
    __shared__ float Wsm[JC][MI][NHEADS];  // 4 KB weights
    __shared__ float f1s[MI][NHEADS];
    __shared__ float msh[MI][NHEADS];
    __shared__ float dred[256];
    __shared__ float dsh[MI * NHEADS];
    __shared__ float4 red4[256];

    const int t  = threadIdx.x;
    const int i0 = blockIdx.x * MI;

    if (t < MI * NHEADS) {
        int il = t >> 2, h = t & 3;
        float f1 = g_f1[h * N_NODES + i0 + il];
        float m  = f1 + g_fmax2[h];
        m = (m > 0.f) ? m : 0.2f * m;     // lrelu of the upper bound
        f1s[il][h] = f1;
        msh[il][h] = m;
    }
    __syncthreads();

    // staging mapping: thread -> fixed (il,h), 4 jj values
    const int sc  = t & 31;
    const int sil = sc >> 2, sh = sc & 3;
    const int sjb = t >> 5;               // 0..7
    const float sf1 = f1s[sil][sh];
    const float smv = msh[sil][sh];
    const float* __restrict__ f2h = &g_f2[sh * N_NODES];

    // FMA mapping: thread -> (jg, h, f-quad)
    const int jg = t >> 6;                // 0..3
    const int hq = t & 63;                // float4 column in XW row
    const int h  = hq >> 4;

    float4 acc[MI];
#pragma unroll
    for (int il = 0; il < MI; il++) acc[il] = make_float4(0.f, 0.f, 0.f, 0.f);
    float dacc = 0.f;

    const float4* __restrict__ xw4 = (const float4*)g_XW;

    for (int j0 = 0; j0 < N_NODES; j0 += JC) {
        // stage A chunk (coalesced)
        As[t >> 5][t & 31] = A[(size_t)(i0 + (t >> 5)) * N_NODES + j0 + (t & 31)];
        __syncthreads();
        // stage weights
#pragma unroll
        for (int r = 0; r < 4; r++) {
            int jj = sjb + (r << 3);
            int a  = As[sil][jj];
            float s = sf1 + f2h[j0 + jj];
            s = (s > 0.f) ? s : 0.2f * s;
            float w = a ? __expf(s - smv) : 0.f;
            Wsm[jj][sil][sh] = w;
            dacc += w;
        }
        __syncthreads();
        // accumulate
#pragma unroll 4
        for (int u = 0; u < 8; u++) {
            int jj = (jg << 3) + u;
            float4 xw = xw4[(size_t)(j0 + jj) * 64 + hq];
#pragma unroll
            for (int il = 0; il < MI; il++) {
                float w = Wsm[jj][il][h];
                acc[il].x += w * xw.x;
                acc[il].y += w * xw.y;
                acc[il].z += w * xw.z;
                acc[il].w += w * xw.w;
            }
        }
        __syncthreads();
    }

    // reduce denominators: 8 threads (sjb) share each (il,h)=sc
    dred[t] = dacc;
    __syncthreads();
    if (t < 32) {
        float d = 0.f;
        for (int s = t; s < 256; s += 32) d += dred[s];
        dsh[t] = d;                        // index (il<<2)|h
    }
    __syncthreads();

    // reduce numerators across jg, normalize, ELU, store
    for (int il = 0; il < MI; il++) {
        red4[t] = acc[il];
        __syncthreads();
        if (t < 64) {
            float4 a = red4[t], b = red4[t + 64], c = red4[t + 128], d4 = red4[t + 192];
            float4 s;
            s.x = a.x + b.x + c.x + d4.x;
            s.y = a.y + b.y + c.y + d4.y;
            s.z = a.z + b.z + c.z + d4.z;
            s.w = a.w + b.w + c.w + d4.w;
            int h2 = t >> 4;
            float inv = 1.f / dsh[(il << 2) | h2];
            s.x *= inv; s.y *= inv; s.z *= inv; s.w *= inv;
            s.x = (s.x > 0.f) ? s.x : (__expf(s.x) - 1.f);
            s.y = (s.y > 0.f) ? s.y : (__expf(s.y) - 1.f);
            s.z = (s.z > 0.f) ? s.z : (__expf(s.z) - 1.f);
            s.w = (s.w > 0.f) ? s.w : (__expf(s.w) - 1.f);
            ((float4*)out)[(size_t)(i0 + il) * 64 + t] = s;
        }
        __syncthreads();
    }
}

// ---------------- launch ----------------------------------------------------
extern "C" void kernel_launch(void* const* d_in, const int* in_sizes, int n_in,
                              void* d_out, int out_size) {
    const float* X     = (const float*)d_in[0];
    const int*   A     = (const int*)d_in[1];
    const float* W     = (const float*)d_in[2];
    const float* a_src = (const float*)d_in[3];
    const float* a_dst = (const float*)d_in[4];
    float* out = (float*)d_out;

    dim3 ggrid(HF / 64, N_NODES / 64);
    gemm_xw<<<ggrid, 256>>>(X, W);
    f_kernel<<<N_NODES, 256>>>(a_src, a_dst);
    fmax_kernel<<<NHEADS, 256>>>();
    agg_kernel<<<N_NODES / MI, 256>>>(A, out);
}

// round 3
// speedup vs baseline: 1.9808x; 1.9808x over previous
#include <cuda_runtime.h>
#include <cuda_fp16.h>
#include <cstdint>

#define N_NODES 4096
#define FIN     512
#define NHEADS  4
#define FDIM    64
#define HF      256
#define NW      (N_NODES / 32)   // 128 packed words per A row

// ---------------- device scratch --------------------------------------------
__device__ float    g_XW[(size_t)N_NODES * HF];      // 4 MB  [node][hf] fp32
__device__ __half   g_XWTh[(size_t)HF * N_NODES];    // 2 MB  [hf][node] fp16
__device__ unsigned g_Apack[(size_t)N_NODES * NW];   // 2 MB  bitmask
__device__ float    g_f1[NHEADS * N_NODES];
__device__ float    g_f2[NHEADS * N_NODES];
__device__ float    g_fmax2[NHEADS];

// ---------------- kernel 0: pack A into bitmask -----------------------------
__global__ void __launch_bounds__(128) pack_a(const int* __restrict__ A) {
    const int row = blockIdx.x, w = threadIdx.x >> 5, lane = threadIdx.x & 31;
    const int* ar = A + (size_t)row * N_NODES;
    for (int wi = w; wi < NW; wi += 4) {
        int v = ar[wi * 32 + lane];
        unsigned b = __ballot_sync(0xffffffffu, v != 0);
        if (lane == 0) g_Apack[(size_t)row * NW + wi] = b;
    }
}

// ---------------- kernel 1: XW = X @ W  (fp32) + fp16 transposed copy -------
__global__ void __launch_bounds__(256) gemm_xw(const float* __restrict__ X,
                                               const float* __restrict__ W) {
    __shared__ float Xs[16][65];
    __shared__ float Ws[16][64];
    const int t   = threadIdx.x;
    const int bn0 = blockIdx.x * 64;
    const int bm0 = blockIdx.y * 64;
    const int rb  = (t >> 4) << 2;
    const int cb  = (t & 15) << 2;

    float acc[4][4];
#pragma unroll
    for (int i = 0; i < 4; i++)
#pragma unroll
        for (int j = 0; j < 4; j++) acc[i][j] = 0.f;

    for (int k0 = 0; k0 < FIN; k0 += 16) {
#pragma unroll
        for (int i = 0; i < 4; i++) {
            int e  = t + i * 256;
            int ar = e >> 4, ac = e & 15;
            Xs[ac][ar] = X[(size_t)(bm0 + ar) * FIN + k0 + ac];
            int br = e >> 6, bc = e & 63;
            Ws[br][bc] = W[(size_t)(k0 + br) * HF + bn0 + bc];
        }
        __syncthreads();
#pragma unroll
        for (int k = 0; k < 16; k++) {
            float av[4], bv[4];
#pragma unroll
            for (int i = 0; i < 4; i++) av[i] = Xs[k][rb + i];
#pragma unroll
            for (int j = 0; j < 4; j++) bv[j] = Ws[k][cb + j];
#pragma unroll
            for (int i = 0; i < 4; i++)
#pragma unroll
                for (int j = 0; j < 4; j++) acc[i][j] += av[i] * bv[j];
        }
        __syncthreads();
    }
#pragma unroll
    for (int i = 0; i < 4; i++)
#pragma unroll
        for (int j = 0; j < 4; j++)
            g_XW[(size_t)(bm0 + rb + i) * HF + bn0 + cb + j] = acc[i][j];
    // fp16 transposed copy: g_XWTh[hf][node]
#pragma unroll
    for (int j = 0; j < 4; j++) {
        __half2 p0 = __floats2half2_rn(acc[0][j], acc[1][j]);
        __half2 p1 = __floats2half2_rn(acc[2][j], acc[3][j]);
        uint2 v;
        v.x = *reinterpret_cast<unsigned*>(&p0);
        v.y = *reinterpret_cast<unsigned*>(&p1);
        *(uint2*)&g_XWTh[(size_t)(bn0 + cb + j) * N_NODES + bm0 + rb] = v;
    }
}

// ---------------- kernel 2: f1[h,n], f2[h,n] --------------------------------
__global__ void __launch_bounds__(256) f_kernel(const float* __restrict__ a_src,
                                                const float* __restrict__ a_dst) {
    const int n = blockIdx.x, t = threadIdx.x;
    float xw = g_XW[(size_t)n * HF + t];
    float s1 = xw * a_src[t];
    float s2 = xw * a_dst[t];
#pragma unroll
    for (int o = 16; o > 0; o >>= 1) {
        s1 += __shfl_down_sync(0xffffffffu, s1, o);
        s2 += __shfl_down_sync(0xffffffffu, s2, o);
    }
    __shared__ float w1[8], w2[8];
    if ((t & 31) == 0) { w1[t >> 5] = s1; w2[t >> 5] = s2; }
    __syncthreads();
    if (t < NHEADS) {
        g_f1[t * N_NODES + n] = w1[2 * t] + w1[2 * t + 1];
        g_f2[t * N_NODES + n] = w2[2 * t] + w2[2 * t + 1];
    }
}

// ---------------- kernel 3: fmax2[h] ----------------------------------------
__global__ void __launch_bounds__(256) fmax_kernel() {
    const int h = blockIdx.x, t = threadIdx.x;
    float m = -3.0e38f;
    for (int j = t; j < N_NODES; j += 256) m = fmaxf(m, g_f2[h * N_NODES + j]);
#pragma unroll
    for (int o = 16; o > 0; o >>= 1)
        m = fmaxf(m, __shfl_down_sync(0xffffffffu, m, o));
    __shared__ float wm[8];
    if ((t & 31) == 0) wm[t >> 5] = m;
    __syncthreads();
    if (t == 0) {
        float r = wm[0];
#pragma unroll
        for (int w = 1; w < 8; w++) r = fmaxf(r, wm[w]);
        g_fmax2[h] = r;
    }
}

// ---------------- helpers ----------------------------------------------------
__device__ __forceinline__ unsigned packh2(float a, float b) {
    __half2 h = __floats2half2_rn(a, b);
    return *reinterpret_cast<unsigned*>(&h);
}
__device__ __forceinline__ float lrelu(float s) { return fmaxf(s, 0.2f * s); }
__device__ __forceinline__ float eluf(float x) { return x > 0.f ? x : (__expf(x) - 1.f); }

// ---------------- kernel 4: HMMA fp16 masked-softmax aggregation ------------
// CTA = (i-tile of 128 rows, head h); warp owns a 16x64 output tile.
// P is computed directly in the mma.m16n8k16 A-fragment register layout.
#define KC 128
#define XS_STRIDE 136   // halves per smem row (272 B) -> conflict-free B LDS

__global__ void __launch_bounds__(256, 1) agg_mma(float* __restrict__ out) {
    __shared__ __align__(16) __half xs[64][XS_STRIDE];  // 17 KB XW^T tile
    __shared__ __align__(16) float f2s[KC];

    const int t = threadIdx.x, wid = t >> 5, lane = t & 31;
    const int h  = blockIdx.x & 3;
    const int i0 = (blockIdx.x >> 2) << 7;
    const int g  = lane >> 2;        // fragment group row 0..7
    const int q4 = lane & 3;         // fragment thread-in-group
    const int jb = q4 * 2;           // fragment k offset
    const int r0 = wid * 16 + g;     // local row (and r0+8)

    const float fm = g_fmax2[h];
    const float f1a = g_f1[h * N_NODES + i0 + r0];
    const float f1b = g_f1[h * N_NODES + i0 + r0 + 8];
    const float ma = lrelu(f1a + fm);
    const float mb = lrelu(f1b + fm);

    const float*    f2base = g_f2 + h * N_NODES;
    const unsigned* apA = g_Apack + (size_t)(i0 + r0) * NW;
    const unsigned* apB = apA + (size_t)8 * NW;
    const __half*   xwt = g_XWTh + (size_t)h * FDIM * N_NODES;

    float acc[8][4];
#pragma unroll
    for (int nt = 0; nt < 8; nt++)
#pragma unroll
        for (int k = 0; k < 4; k++) acc[nt][k] = 0.f;
    float dacc0 = 0.f, dacc1 = 0.f;

    for (int c = 0; c < N_NODES / KC; c++) {
        const int j0 = c * KC;
        __syncthreads();
        // stage XW^T tile [64 f][128 j] fp16 (coalesced 16B loads)
#pragma unroll
        for (int q = 0; q < 4; q++) {
            int e = t + q * 256;
            int f = e >> 4, cc = e & 15;
            *(uint4*)&xs[f][cc * 8] = *(const uint4*)(xwt + (size_t)f * N_NODES + j0 + cc * 8);
        }
        if (t < 32) ((float4*)f2s)[t] = ((const float4*)(f2base + j0))[t];
        __syncthreads();

        // mask words for this chunk (one LDG.128 per row)
        uint4 mua = *(const uint4*)&apA[j0 >> 5];
        uint4 mub = *(const uint4*)&apB[j0 >> 5];
        unsigned mwa[4] = {mua.x, mua.y, mua.z, mua.w};
        unsigned mwb[4] = {mub.x, mub.y, mub.z, mub.w};

#pragma unroll
        for (int ks = 0; ks < 8; ks++) {
            const int kb = ks * 16;
            const float2 fA = *(const float2*)&f2s[kb + jb];
            const float2 fB = *(const float2*)&f2s[kb + jb + 8];
            const unsigned ba = mwa[ks >> 1] >> ((ks & 1) * 16 + jb);
            const unsigned bb = mwb[ks >> 1] >> ((ks & 1) * 16 + jb);

            // row r0 (a-lane), 4 j positions: jb, jb+1, jb+8, jb+9
            float e00 = (ba & 1u)   ? __expf(lrelu(f1a + fA.x) - ma) : 0.f;
            float e01 = (ba & 2u)   ? __expf(lrelu(f1a + fA.y) - ma) : 0.f;
            float e08 = (ba & 256u) ? __expf(lrelu(f1a + fB.x) - ma) : 0.f;
            float e09 = (ba & 512u) ? __expf(lrelu(f1a + fB.y) - ma) : 0.f;
            // row r0+8 (b-lane)
            float e10 = (bb & 1u)   ? __expf(lrelu(f1b + fA.x) - mb) : 0.f;
            float e11 = (bb & 2u)   ? __expf(lrelu(f1b + fA.y) - mb) : 0.f;
            float e18 = (bb & 256u) ? __expf(lrelu(f1b + fB.x) - mb) : 0.f;
            float e19 = (bb & 512u) ? __expf(lrelu(f1b + fB.y) - mb) : 0.f;

            dacc0 += (e00 + e01) + (e08 + e09);
            dacc1 += (e10 + e11) + (e18 + e19);

            const unsigned a0 = packh2(e00, e01);
            const unsigned a1 = packh2(e10, e11);
            const unsigned a2 = packh2(e08, e09);
            const unsigned a3 = packh2(e18, e19);

#pragma unroll
            for (int nt = 0; nt < 8; nt++) {
                const __half* bp = &xs[nt * 8 + g][kb + jb];
                const unsigned b0 = *(const unsigned*)bp;
                const unsigned b1 = *(const unsigned*)(bp + 8);
                asm volatile(
                    "mma.sync.aligned.m16n8k16.row.col.f32.f16.f16.f32 "
                    "{%0,%1,%2,%3}, {%4,%5,%6,%7}, {%8,%9}, {%0,%1,%2,%3};"
                    : "+f"(acc[nt][0]), "+f"(acc[nt][1]), "+f"(acc[nt][2]), "+f"(acc[nt][3])
                    : "r"(a0), "r"(a1), "r"(a2), "r"(a3), "r"(b0), "r"(b1));
            }
        }
    }

    // denominators: 4 threads (q4) share each row pair
    dacc0 += __shfl_xor_sync(0xffffffffu, dacc0, 1);
    dacc0 += __shfl_xor_sync(0xffffffffu, dacc0, 2);
    dacc1 += __shfl_xor_sync(0xffffffffu, dacc1, 1);
    dacc1 += __shfl_xor_sync(0xffffffffu, dacc1, 2);
    const float inv0 = 1.f / dacc0;
    const float inv1 = 1.f / dacc1;

    // epilogue: normalize + ELU + store (c-fragment layout)
    float* ob0 = out + (size_t)(i0 + r0) * HF + h * FDIM + jb;
    float* ob1 = ob0 + (size_t)8 * HF;
#pragma unroll
    for (int nt = 0; nt < 8; nt++) {
        float2 v0, v1;
        v0.x = eluf(acc[nt][0] * inv0);
        v0.y = eluf(acc[nt][1] * inv0);
        v1.x = eluf(acc[nt][2] * inv1);
        v1.y = eluf(acc[nt][3] * inv1);
        *(float2*)(ob0 + nt * 8) = v0;
        *(float2*)(ob1 + nt * 8) = v1;
    }
}

// ---------------- launch ----------------------------------------------------
extern "C" void kernel_launch(void* const* d_in, const int* in_sizes, int n_in,
                              void* d_out, int out_size) {
    const float* X     = (const float*)d_in[0];
    const int*   A     = (const int*)d_in[1];
    const float* W     = (const float*)d_in[2];
    const float* a_src = (const float*)d_in[3];
    const float* a_dst = (const float*)d_in[4];
    float* out = (float*)d_out;

    pack_a<<<N_NODES, 128>>>(A);
    dim3 ggrid(HF / 64, N_NODES / 64);
    gemm_xw<<<ggrid, 256>>>(X, W);
    f_kernel<<<N_NODES, 256>>>(a_src, a_dst);
    fmax_kernel<<<NHEADS, 256>>>();
    agg_mma<<<(N_NODES / 128) * NHEADS, 256>>>(out);
}

// round 4
// speedup vs baseline: 4.0885x; 2.0641x over previous
#include <cuda_runtime.h>
#include <cuda_fp16.h>
#include <cstdint>

#define N_NODES 4096
#define FIN     512
#define NHEADS  4
#define FDIM    64
#define HF      256
#define NW      (N_NODES / 32)   // 128 packed words per A row
#define LOG2E   1.4426950408889634f

// ---------------- device scratch --------------------------------------------
__device__ float    g_XW[(size_t)N_NODES * HF];      // 4 MB  [node][hf] fp32
__device__ __half   g_XWTh[(size_t)HF * N_NODES];    // 2 MB  [hf][node] fp16
__device__ unsigned g_Apack[(size_t)N_NODES * NW];   // 2 MB  bitmask
__device__ float    g_f1[NHEADS * N_NODES];
__device__ float    g_f2[NHEADS * N_NODES];
__device__ int      g_fmax2i[NHEADS];                // monotonic-int encoded max

__device__ __forceinline__ int enc_f(float f) {
    int e = __float_as_int(f);
    return (e >= 0) ? e : (e ^ 0x7FFFFFFF);
}
__device__ __forceinline__ float dec_f(int v) {
    return __int_as_float(v >= 0 ? v : (v ^ 0x7FFFFFFF));
}
__device__ __forceinline__ uint32_t f2tf32(float x) {
    uint32_t u;
    asm("cvt.rna.tf32.f32 %0, %1;" : "=r"(u) : "f"(x));
    return u;
}
__device__ __forceinline__ float ex2f(float x) {
    float r;
    asm("ex2.approx.ftz.f32 %0, %1;" : "=f"(r) : "f"(x));
    return r;
}
__device__ __forceinline__ unsigned packh2(float a, float b) {
    __half2 h = __floats2half2_rn(a, b);
    return *reinterpret_cast<unsigned*>(&h);
}
__device__ __forceinline__ float lrelu(float s) { return fmaxf(s, 0.2f * s); }
__device__ __forceinline__ float eluf(float x) { return x > 0.f ? x : (__expf(x) - 1.f); }

// ---------------- kernel 0: pack A into bitmask (+ init fmax) ---------------
__global__ void __launch_bounds__(128) pack_a(const int* __restrict__ A) {
    if (blockIdx.x == 0 && threadIdx.x < NHEADS) g_fmax2i[threadIdx.x] = 0x80000000;
    const int row = blockIdx.x, w = threadIdx.x >> 5, lane = threadIdx.x & 31;
    const int* ar = A + (size_t)row * N_NODES;
    for (int wi = w; wi < NW; wi += 4) {
        int v = ar[wi * 32 + lane];
        unsigned b = __ballot_sync(0xffffffffu, v != 0);
        if (lane == 0) g_Apack[(size_t)row * NW + wi] = b;
    }
}

// ---------------- kernel 1: XW = X @ W  via tf32 mma.sync -------------------
// M=4096, N=256, K=512. CTA: 128x64, BK=32, 8 warps (2n x 4m), warp tile 32x32.
__global__ void __launch_bounds__(256) gemm_xw(const float* __restrict__ X,
                                               const float* __restrict__ W) {
    __shared__ uint32_t XsT[32][136];   // [k][m] tf32, stride%32==8 -> frag LDS conflict-free
    __shared__ uint32_t Ws[32][72];     // [k][n] tf32

    const int t = threadIdx.x, wid = t >> 5, lane = t & 31;
    const int g = lane >> 2, q4 = lane & 3;
    const int bn0 = blockIdx.x * 64;
    const int bm0 = blockIdx.y * 128;
    const int wm = (wid & 3) * 32;      // warp m offset
    const int wn = (wid >> 2) * 32;     // warp n offset

    float acc[2][4][4];
#pragma unroll
    for (int mt = 0; mt < 2; mt++)
#pragma unroll
        for (int nt = 0; nt < 4; nt++)
#pragma unroll
            for (int k = 0; k < 4; k++) acc[mt][nt][k] = 0.f;

    for (int k0 = 0; k0 < FIN; k0 += 32) {
        // stage X tile (transposed to [k][m], tf32)
#pragma unroll
        for (int p = 0; p < 4; p++) {
            int idx = t + p * 256;
            int m = idx & 127, kq = idx >> 7;        // kq 0..7
            float4 v = *(const float4*)(X + (size_t)(bm0 + m) * FIN + k0 + kq * 4);
            XsT[kq * 4 + 0][m] = f2tf32(v.x);
            XsT[kq * 4 + 1][m] = f2tf32(v.y);
            XsT[kq * 4 + 2][m] = f2tf32(v.z);
            XsT[kq * 4 + 3][m] = f2tf32(v.w);
        }
        // stage W tile [k][n] tf32
#pragma unroll
        for (int p = 0; p < 2; p++) {
            int idx = t + p * 256;
            int k = idx >> 4, n4 = idx & 15;
            float4 v = *(const float4*)(W + (size_t)(k0 + k) * HF + bn0 + n4 * 4);
            Ws[k][n4 * 4 + 0] = f2tf32(v.x);
            Ws[k][n4 * 4 + 1] = f2tf32(v.y);
            Ws[k][n4 * 4 + 2] = f2tf32(v.z);
            Ws[k][n4 * 4 + 3] = f2tf32(v.w);
        }
        __syncthreads();

#pragma unroll
        for (int ks = 0; ks < 4; ks++) {
            const int kk = ks * 8;
            uint32_t b0[4], b1[4];
#pragma unroll
            for (int nt = 0; nt < 4; nt++) {
                b0[nt] = Ws[kk + q4][wn + nt * 8 + g];
                b1[nt] = Ws[kk + 4 + q4][wn + nt * 8 + g];
            }
#pragma unroll
            for (int mt = 0; mt < 2; mt++) {
                const int rb = wm + mt * 16;
                uint32_t a0 = XsT[kk + q4][rb + g];
                uint32_t a1 = XsT[kk + q4][rb + g + 8];
                uint32_t a2 = XsT[kk + q4 + 4][rb + g];
                uint32_t a3 = XsT[kk + q4 + 4][rb + g + 8];
#pragma unroll
                for (int nt = 0; nt < 4; nt++) {
                    asm volatile(
                        "mma.sync.aligned.m16n8k8.row.col.f32.tf32.tf32.f32 "
                        "{%0,%1,%2,%3}, {%4,%5,%6,%7}, {%8,%9}, {%0,%1,%2,%3};"
                        : "+f"(acc[mt][nt][0]), "+f"(acc[mt][nt][1]),
                          "+f"(acc[mt][nt][2]), "+f"(acc[mt][nt][3])
                        : "r"(a0), "r"(a1), "r"(a2), "r"(a3), "r"(b0[nt]), "r"(b1[nt]));
                }
            }
        }
        __syncthreads();
    }

    // epilogue: write g_XW fp32
#pragma unroll
    for (int mt = 0; mt < 2; mt++) {
        const int r = bm0 + wm + mt * 16 + g;
#pragma unroll
        for (int nt = 0; nt < 4; nt++) {
            const int c = bn0 + wn + nt * 8 + 2 * q4;
            *(float2*)&g_XW[(size_t)r * HF + c]       = make_float2(acc[mt][nt][0], acc[mt][nt][1]);
            *(float2*)&g_XW[(size_t)(r + 8) * HF + c] = make_float2(acc[mt][nt][2], acc[mt][nt][3]);
        }
    }
}

// ---------------- kernel 1b: transpose XW -> XWTh fp16 ----------------------
// block: 64 nodes x 64 hf tile, 256 threads
__global__ void __launch_bounds__(256) transpose_xw() {
    __shared__ float ts[64][65];
    const int t = threadIdx.x;
    const int hf0 = blockIdx.x * 64;
    const int n0  = blockIdx.y * 64;
#pragma unroll
    for (int p = 0; p < 4; p++) {
        int e = t + p * 256;
        int node = e >> 4, c4 = e & 15;
        float4 v = *(const float4*)(g_XW + (size_t)(n0 + node) * HF + hf0 + c4 * 4);
        ts[node][c4 * 4 + 0] = v.x;
        ts[node][c4 * 4 + 1] = v.y;
        ts[node][c4 * 4 + 2] = v.z;
        ts[node][c4 * 4 + 3] = v.w;
    }
    __syncthreads();
#pragma unroll
    for (int p = 0; p < 2; p++) {
        int e = t + p * 256;
        int hf = e >> 3, n8 = e & 7;
        uint4 o;
        unsigned* op = (unsigned*)&o;
#pragma unroll
        for (int i = 0; i < 4; i++)
            op[i] = packh2(ts[n8 * 8 + 2 * i][hf], ts[n8 * 8 + 2 * i + 1][hf]);
        *(uint4*)&g_XWTh[(size_t)(hf0 + hf) * N_NODES + n0 + n8 * 8] = o;
    }
}

// ---------------- kernel 2: f1[h,n], f2[h,n] (log2e-scaled) -----------------
__global__ void __launch_bounds__(256) f_kernel(const float* __restrict__ a_src,
                                                const float* __restrict__ a_dst) {
    const int n = blockIdx.x, t = threadIdx.x;
    float xw = g_XW[(size_t)n * HF + t];
    float s1 = xw * a_src[t];
    float s2 = xw * a_dst[t];
#pragma unroll
    for (int o = 16; o > 0; o >>= 1) {
        s1 += __shfl_down_sync(0xffffffffu, s1, o);
        s2 += __shfl_down_sync(0xffffffffu, s2, o);
    }
    __shared__ float w1[8], w2[8];
    if ((t & 31) == 0) { w1[t >> 5] = s1; w2[t >> 5] = s2; }
    __syncthreads();
    if (t < NHEADS) {
        g_f1[t * N_NODES + n] = (w1[2 * t] + w1[2 * t + 1]) * LOG2E;
        g_f2[t * N_NODES + n] = (w2[2 * t] + w2[2 * t + 1]) * LOG2E;
    }
}

// ---------------- kernel 3: fmax via atomicMax ------------------------------
// grid 32 blocks x 128 threads; warp = one head, block covers 128 nodes
__global__ void __launch_bounds__(128) fmax_kernel() {
    const int t = threadIdx.x, h = t >> 5, lane = t & 31;
    const int n0 = blockIdx.x * 128;
    float m = -3.0e38f;
#pragma unroll
    for (int k = 0; k < 4; k++)
        m = fmaxf(m, g_f2[h * N_NODES + n0 + lane + k * 32]);
#pragma unroll
    for (int o = 16; o > 0; o >>= 1)
        m = fmaxf(m, __shfl_xor_sync(0xffffffffu, m, o));
    if (lane == 0) atomicMax(&g_fmax2i[h], enc_f(m));
}

// ---------------- kernel 4: HMMA fp16 masked-softmax aggregation ------------
// CTA = (64-row i-tile, head); 4 warps; warp owns 16x64 output tile.
#define KC 128
#define XS_STRIDE 136

__global__ void __launch_bounds__(128, 2) agg_mma(float* __restrict__ out) {
    __shared__ __align__(16) __half xs[64][XS_STRIDE];  // 17 KB XW^T tile
    __shared__ __align__(16) float f2s[KC];

    const int t = threadIdx.x, wid = t >> 5, lane = t & 31;
    const int h  = blockIdx.x & 3;
    const int i0 = (blockIdx.x >> 2) << 6;
    const int g  = lane >> 2;
    const int q4 = lane & 3;
    const int jb = q4 * 2;
    const int r0 = wid * 16 + g;

    const float fm  = dec_f(g_fmax2i[h]);
    const float f1a = g_f1[h * N_NODES + i0 + r0];
    const float f1b = g_f1[h * N_NODES + i0 + r0 + 8];
    const float ma = lrelu(f1a + fm);
    const float mb = lrelu(f1b + fm);

    const float*    f2base = g_f2 + h * N_NODES;
    const unsigned* apA = g_Apack + (size_t)(i0 + r0) * NW;
    const unsigned* apB = apA + (size_t)8 * NW;
    const __half*   xwt = g_XWTh + (size_t)h * FDIM * N_NODES;

    float acc[8][4];
#pragma unroll
    for (int nt = 0; nt < 8; nt++)
#pragma unroll
        for (int k = 0; k < 4; k++) acc[nt][k] = 0.f;
    float dacc0 = 0.f, dacc1 = 0.f;

    for (int c = 0; c < N_NODES / KC; c++) {
        const int j0 = c * KC;
        __syncthreads();
#pragma unroll
        for (int q = 0; q < 8; q++) {
            int e = t + q * 128;
            int f = e >> 4, cc = e & 15;
            *(uint4*)&xs[f][cc * 8] = *(const uint4*)(xwt + (size_t)f * N_NODES + j0 + cc * 8);
        }
        if (t < 32) ((float4*)f2s)[t] = ((const float4*)(f2base + j0))[t];
        __syncthreads();

        uint4 mua = *(const uint4*)&apA[j0 >> 5];
        uint4 mub = *(const uint4*)&apB[j0 >> 5];
        unsigned mwa[4] = {mua.x, mua.y, mua.z, mua.w};
        unsigned mwb[4] = {mub.x, mub.y, mub.z, mub.w};

#pragma unroll
        for (int ks = 0; ks < 8; ks++) {
            const int kb = ks * 16;
            const float2 fA = *(const float2*)&f2s[kb + jb];
            const float2 fB = *(const float2*)&f2s[kb + jb + 8];
            const unsigned ba = mwa[ks >> 1] >> ((ks & 1) * 16 + jb);
            const unsigned bb = mwb[ks >> 1] >> ((ks & 1) * 16 + jb);

            float e00 = (ba & 1u)   ? ex2f(lrelu(f1a + fA.x) - ma) : 0.f;
            float e01 = (ba & 2u)   ? ex2f(lrelu(f1a + fA.y) - ma) : 0.f;
            float e08 = (ba & 256u) ? ex2f(lrelu(f1a + fB.x) - ma) : 0.f;
            float e09 = (ba & 512u) ? ex2f(lrelu(f1a + fB.y) - ma) : 0.f;
            float e10 = (bb & 1u)   ? ex2f(lrelu(f1b + fA.x) - mb) : 0.f;
            float e11 = (bb & 2u)   ? ex2f(lrelu(f1b + fA.y) - mb) : 0.f;
            float e18 = (bb & 256u) ? ex2f(lrelu(f1b + fB.x) - mb) : 0.f;
            float e19 = (bb & 512u) ? ex2f(lrelu(f1b + fB.y) - mb) : 0.f;

            dacc0 += (e00 + e01) + (e08 + e09);
            dacc1 += (e10 + e11) + (e18 + e19);

            const unsigned a0 = packh2(e00, e01);
            const unsigned a1 = packh2(e10, e11);
            const unsigned a2 = packh2(e08, e09);
            const unsigned a3 = packh2(e18, e19);

#pragma unroll
            for (int nt = 0; nt < 8; nt++) {
                const __half* bp = &xs[nt * 8 + g][kb + jb];
                const unsigned b0 = *(const unsigned*)bp;
                const unsigned b1 = *(const unsigned*)(bp + 8);
                asm volatile(
                    "mma.sync.aligned.m16n8k16.row.col.f32.f16.f16.f32 "
                    "{%0,%1,%2,%3}, {%4,%5,%6,%7}, {%8,%9}, {%0,%1,%2,%3};"
                    : "+f"(acc[nt][0]), "+f"(acc[nt][1]), "+f"(acc[nt][2]), "+f"(acc[nt][3])
                    : "r"(a0), "r"(a1), "r"(a2), "r"(a3), "r"(b0), "r"(b1));
            }
        }
    }

    dacc0 += __shfl_xor_sync(0xffffffffu, dacc0, 1);
    dacc0 += __shfl_xor_sync(0xffffffffu, dacc0, 2);
    dacc1 += __shfl_xor_sync(0xffffffffu, dacc1, 1);
    dacc1 += __shfl_xor_sync(0xffffffffu, dacc1, 2);
    const float inv0 = 1.f / dacc0;
    const float inv1 = 1.f / dacc1;

    float* ob0 = out + (size_t)(i0 + r0) * HF + h * FDIM + jb;
    float* ob1 = ob0 + (size_t)8 * HF;
#pragma unroll
    for (int nt = 0; nt < 8; nt++) {
        float2 v0, v1;
        v0.x = eluf(acc[nt][0] * inv0);
        v0.y = eluf(acc[nt][1] * inv0);
        v1.x = eluf(acc[nt][2] * inv1);
        v1.y = eluf(acc[nt][3] * inv1);
        *(float2*)(ob0 + nt * 8) = v0;
        *(float2*)(ob1 + nt * 8) = v1;
    }
}

// ---------------- launch ----------------------------------------------------
extern "C" void kernel_launch(void* const* d_in, const int* in_sizes, int n_in,
                              void* d_out, int out_size) {
    const float* X     = (const float*)d_in[0];
    const int*   A     = (const int*)d_in[1];
    const float* W     = (const float*)d_in[2];
    const float* a_src = (const float*)d_in[3];
    const float* a_dst = (const float*)d_in[4];
    float* out = (float*)d_out;

    pack_a<<<N_NODES, 128>>>(A);
    dim3 ggrid(HF / 64, N_NODES / 128);
    gemm_xw<<<ggrid, 256>>>(X, W);
    dim3 tgrid(HF / 64, N_NODES / 64);
    transpose_xw<<<tgrid, 256>>>();
    f_kernel<<<N_NODES, 256>>>(a_src, a_dst);
    fmax_kernel<<<N_NODES / 128, 128>>>();
    agg_mma<<<(N_NODES / 64) * NHEADS, 128>>>(out);
}

// round 5
// speedup vs baseline: 4.5526x; 1.1135x over previous
#include <cuda_runtime.h>
#include <cuda_fp16.h>
#include <cstdint>

#define N_NODES 4096
#define FIN     512
#define NHEADS  4
#define FDIM    64
#define HF      256
#define NW      (N_NODES / 32)   // 128 packed words per A row
#define LOG2E   1.4426950408889634f

// ---------------- device scratch --------------------------------------------
__device__ float    g_XW[(size_t)N_NODES * HF];      // 4 MB  [node][hf] fp32
__device__ __half   g_XWTh[(size_t)HF * N_NODES];    // 2 MB  [hf][node] fp16
__device__ unsigned g_Apack[(size_t)N_NODES * NW];   // 2 MB  bitmask
__device__ float    g_f1[NHEADS * N_NODES];
__device__ float    g_f2[NHEADS * N_NODES];
__device__ int      g_fmax2i[NHEADS];                // monotonic-int encoded max

__device__ __forceinline__ int enc_f(float f) {
    int e = __float_as_int(f);
    return (e >= 0) ? e : (e ^ 0x7FFFFFFF);
}
__device__ __forceinline__ float dec_f(int v) {
    return __int_as_float(v >= 0 ? v : (v ^ 0x7FFFFFFF));
}
__device__ __forceinline__ uint32_t f2tf32(float x) {
    uint32_t u;
    asm("cvt.rna.tf32.f32 %0, %1;" : "=r"(u) : "f"(x));
    return u;
}
__device__ __forceinline__ float ex2f(float x) {
    float r;
    asm("ex2.approx.ftz.f32 %0, %1;" : "=f"(r) : "f"(x));
    return r;
}
__device__ __forceinline__ unsigned packh2(float a, float b) {
    __half2 h = __floats2half2_rn(a, b);
    return *reinterpret_cast<unsigned*>(&h);
}
__device__ __forceinline__ float eluf(float x) { return x > 0.f ? x : (__expf(x) - 1.f); }
__device__ __forceinline__ uint32_t smem_u32(const void* p) {
    uint32_t a;
    asm("{ .reg .u64 t; cvta.to.shared.u64 t, %1; cvt.u32.u64 %0, t; }" : "=r"(a) : "l"(p));
    return a;
}

// ---------------- kernel 0: pack A into bitmask (+ init fmax) ---------------
__global__ void __launch_bounds__(128) pack_a(const int* __restrict__ A) {
    if (blockIdx.x == 0 && threadIdx.x < NHEADS) g_fmax2i[threadIdx.x] = (int)0x80000000;
    const int row = blockIdx.x, w = threadIdx.x >> 5, lane = threadIdx.x & 31;
    const int* ar = A + (size_t)row * N_NODES;
    for (int wi = w; wi < NW; wi += 4) {
        int v = ar[wi * 32 + lane];
        unsigned b = __ballot_sync(0xffffffffu, v != 0);
        if (lane == 0) g_Apack[(size_t)row * NW + wi] = b;
    }
}

// ---------------- kernel 1: XW = X @ W  via tf32 mma.sync -------------------
__global__ void __launch_bounds__(256) gemm_xw(const float* __restrict__ X,
                                               const float* __restrict__ W) {
    __shared__ uint32_t XsT[32][136];
    __shared__ uint32_t Ws[32][72];

    const int t = threadIdx.x, wid = t >> 5, lane = t & 31;
    const int g = lane >> 2, q4 = lane & 3;
    const int bn0 = blockIdx.x * 64;
    const int bm0 = blockIdx.y * 128;
    const int wm = (wid & 3) * 32;
    const int wn = (wid >> 2) * 32;

    float acc[2][4][4];
#pragma unroll
    for (int mt = 0; mt < 2; mt++)
#pragma unroll
        for (int nt = 0; nt < 4; nt++)
#pragma unroll
            for (int k = 0; k < 4; k++) acc[mt][nt][k] = 0.f;

    for (int k0 = 0; k0 < FIN; k0 += 32) {
#pragma unroll
        for (int p = 0; p < 4; p++) {
            int idx = t + p * 256;
            int m = idx & 127, kq = idx >> 7;
            float4 v = *(const float4*)(X + (size_t)(bm0 + m) * FIN + k0 + kq * 4);
            XsT[kq * 4 + 0][m] = f2tf32(v.x);
            XsT[kq * 4 + 1][m] = f2tf32(v.y);
            XsT[kq * 4 + 2][m] = f2tf32(v.z);
            XsT[kq * 4 + 3][m] = f2tf32(v.w);
        }
#pragma unroll
        for (int p = 0; p < 2; p++) {
            int idx = t + p * 256;
            int k = idx >> 4, n4 = idx & 15;
            float4 v = *(const float4*)(W + (size_t)(k0 + k) * HF + bn0 + n4 * 4);
            Ws[k][n4 * 4 + 0] = f2tf32(v.x);
            Ws[k][n4 * 4 + 1] = f2tf32(v.y);
            Ws[k][n4 * 4 + 2] = f2tf32(v.z);
            Ws[k][n4 * 4 + 3] = f2tf32(v.w);
        }
        __syncthreads();

#pragma unroll
        for (int ks = 0; ks < 4; ks++) {
            const int kk = ks * 8;
            uint32_t b0[4], b1[4];
#pragma unroll
            for (int nt = 0; nt < 4; nt++) {
                b0[nt] = Ws[kk + q4][wn + nt * 8 + g];
                b1[nt] = Ws[kk + 4 + q4][wn + nt * 8 + g];
            }
#pragma unroll
            for (int mt = 0; mt < 2; mt++) {
                const int rb = wm + mt * 16;
                uint32_t a0 = XsT[kk + q4][rb + g];
                uint32_t a1 = XsT[kk + q4][rb + g + 8];
                uint32_t a2 = XsT[kk + q4 + 4][rb + g];
                uint32_t a3 = XsT[kk + q4 + 4][rb + g + 8];
#pragma unroll
                for (int nt = 0; nt < 4; nt++) {
                    asm volatile(
                        "mma.sync.aligned.m16n8k8.row.col.f32.tf32.tf32.f32 "
                        "{%0,%1,%2,%3}, {%4,%5,%6,%7}, {%8,%9}, {%0,%1,%2,%3};"
                        : "+f"(acc[mt][nt][0]), "+f"(acc[mt][nt][1]),
                          "+f"(acc[mt][nt][2]), "+f"(acc[mt][nt][3])
                        : "r"(a0), "r"(a1), "r"(a2), "r"(a3), "r"(b0[nt]), "r"(b1[nt]));
                }
            }
        }
        __syncthreads();
    }

#pragma unroll
    for (int mt = 0; mt < 2; mt++) {
        const int r = bm0 + wm + mt * 16 + g;
#pragma unroll
        for (int nt = 0; nt < 4; nt++) {
            const int c = bn0 + wn + nt * 8 + 2 * q4;
            *(float2*)&g_XW[(size_t)r * HF + c]       = make_float2(acc[mt][nt][0], acc[mt][nt][1]);
            *(float2*)&g_XW[(size_t)(r + 8) * HF + c] = make_float2(acc[mt][nt][2], acc[mt][nt][3]);
        }
    }
}

// ---------------- kernel 1b: transpose + f1/f2/fmax (fused) -----------------
// block: 64 nodes x 64 hf (one full head) tile, 256 threads
__global__ void __launch_bounds__(256) transpose_xw(const float* __restrict__ a_src,
                                                    const float* __restrict__ a_dst) {
    __shared__ float ts[64][65];
    __shared__ float as[64], ad[64];
    __shared__ float f2loc[64];
    const int t = threadIdx.x;
    const int hf0 = blockIdx.x * 64;       // == head h * 64
    const int n0  = blockIdx.y * 64;
    const int h   = blockIdx.x;

    if (t < 64) { as[t] = a_src[hf0 + t]; ad[t] = a_dst[hf0 + t]; }
#pragma unroll
    for (int p = 0; p < 4; p++) {
        int e = t + p * 256;
        int node = e >> 4, c4 = e & 15;
        float4 v = *(const float4*)(g_XW + (size_t)(n0 + node) * HF + hf0 + c4 * 4);
        ts[node][c4 * 4 + 0] = v.x;
        ts[node][c4 * 4 + 1] = v.y;
        ts[node][c4 * 4 + 2] = v.z;
        ts[node][c4 * 4 + 3] = v.w;
    }
    __syncthreads();
    // fp16 transposed store
#pragma unroll
    for (int p = 0; p < 2; p++) {
        int e = t + p * 256;
        int hf = e >> 3, n8 = e & 7;
        uint4 o;
        unsigned* op = (unsigned*)&o;
#pragma unroll
        for (int i = 0; i < 4; i++)
            op[i] = packh2(ts[n8 * 8 + 2 * i][hf], ts[n8 * 8 + 2 * i + 1][hf]);
        *(uint4*)&g_XWTh[(size_t)(hf0 + hf) * N_NODES + n0 + n8 * 8] = o;
    }
    // f1/f2 (exact head dot products; tile covers the full head)
    const int node = t >> 2, q = t & 3;
    float s1 = 0.f, s2 = 0.f;
#pragma unroll
    for (int i = 0; i < 16; i++) {
        float x = ts[node][q * 16 + i];
        s1 += x * as[q * 16 + i];
        s2 += x * ad[q * 16 + i];
    }
    s1 += __shfl_xor_sync(0xffffffffu, s1, 1);
    s1 += __shfl_xor_sync(0xffffffffu, s1, 2);
    s2 += __shfl_xor_sync(0xffffffffu, s2, 1);
    s2 += __shfl_xor_sync(0xffffffffu, s2, 2);
    if (q == 0) {
        float f2v = s2 * LOG2E;
        g_f1[h * N_NODES + n0 + node] = s1 * LOG2E;
        g_f2[h * N_NODES + n0 + node] = f2v;
        f2loc[node] = f2v;
    }
    __syncthreads();
    if (t < 32) {
        float m = fmaxf(f2loc[t], f2loc[t + 32]);
#pragma unroll
        for (int o = 16; o > 0; o >>= 1)
            m = fmaxf(m, __shfl_xor_sync(0xffffffffu, m, o));
        if (t == 0) atomicMax(&g_fmax2i[h], enc_f(m));
    }
}

// ---------------- kernel 4: HMMA fp16 masked-softmax aggregation ------------
// CTA = (64-row i-tile, head); 4 warps; warp owns 16x64 output tile.
// B fragments via ldmatrix.x4; denominator via ones-column HMMA.
#define KC 128
#define XS_STRIDE 136   // halves; 272 B row -> ldmatrix conflict-free

__global__ void __launch_bounds__(128, 4) agg_mma(float* __restrict__ out) {
    __shared__ __align__(16) __half xs[64][XS_STRIDE];  // 17 KB XW^T tile
    __shared__ __align__(16) float f2s[KC];

    const int t = threadIdx.x, wid = t >> 5, lane = t & 31;
    const int h  = blockIdx.x & 3;
    const int i0 = (blockIdx.x >> 2) << 6;
    const int g  = lane >> 2;
    const int q4 = lane & 3;
    const int jb = q4 * 2;
    const int r0 = wid * 16 + g;

    const float fm  = dec_f(g_fmax2i[h]);
    const float f1a = g_f1[h * N_NODES + i0 + r0];
    const float f1b = g_f1[h * N_NODES + i0 + r0 + 8];
    const float ma = fmaxf(f1a + fm, 0.2f * (f1a + fm));
    const float mb = fmaxf(f1b + fm, 0.2f * (f1b + fm));
    // folded row constants: lrelu(f1+f2)-m = max((f1-m)+f2, 0.2*f2+(0.2*f1-m))
    const float A1 = f1a - ma, A5 = 0.2f * f1a - ma;
    const float B1 = f1b - mb, B5 = 0.2f * f1b - mb;

    const float*    f2base = g_f2 + h * N_NODES;
    const unsigned* apA = g_Apack + (size_t)(i0 + r0) * NW;
    const unsigned* apB = apA + (size_t)8 * NW;
    const __half*   xwt = g_XWTh + (size_t)h * FDIM * N_NODES;

    // ldmatrix per-lane base: matrix m = lane>>3 (nt-parity, k-half), row = lane&7
    const int ldrow = lane & 7, msel = lane >> 3;
    const uint32_t xsb = smem_u32(&xs[0][0]);
    const uint32_t ldBase = xsb + (uint32_t)((((msel >> 1) * 8 + ldrow) * XS_STRIDE + (msel & 1) * 8) * 2);

    float acc[8][4];
#pragma unroll
    for (int nt = 0; nt < 8; nt++)
#pragma unroll
        for (int k = 0; k < 4; k++) acc[nt][k] = 0.f;
    float accd[4] = {0.f, 0.f, 0.f, 0.f};
    const unsigned bones = 0x3C003C00u;   // half2(1.0, 1.0)

    for (int c = 0; c < N_NODES / KC; c++) {
        const int j0 = c * KC;
        __syncthreads();
#pragma unroll
        for (int q = 0; q < 8; q++) {
            int e = t + q * 128;
            int f = e >> 4, cc = e & 15;
            *(uint4*)&xs[f][cc * 8] = *(const uint4*)(xwt + (size_t)f * N_NODES + j0 + cc * 8);
        }
        if (t < 32) ((float4*)f2s)[t] = ((const float4*)(f2base + j0))[t];
        __syncthreads();

        uint4 mua = *(const uint4*)&apA[j0 >> 5];
        uint4 mub = *(const uint4*)&apB[j0 >> 5];
        unsigned mwa[4] = {mua.x, mua.y, mua.z, mua.w};
        unsigned mwb[4] = {mub.x, mub.y, mub.z, mub.w};

#pragma unroll
        for (int ks = 0; ks < 8; ks++) {
            const int kb = ks * 16;
            const float2 fA = *(const float2*)&f2s[kb + jb];
            const float2 fB = *(const float2*)&f2s[kb + jb + 8];
            const unsigned ba = mwa[ks >> 1] >> ((ks & 1) * 16 + jb);
            const unsigned bb = mwb[ks >> 1] >> ((ks & 1) * 16 + jb);

            float e00 = (ba & 1u)   ? ex2f(fmaxf(A1 + fA.x, fmaf(0.2f, fA.x, A5))) : 0.f;
            float e01 = (ba & 2u)   ? ex2f(fmaxf(A1 + fA.y, fmaf(0.2f, fA.y, A5))) : 0.f;
            float e08 = (ba & 256u) ? ex2f(fmaxf(A1 + fB.x, fmaf(0.2f, fB.x, A5))) : 0.f;
            float e09 = (ba & 512u) ? ex2f(fmaxf(A1 + fB.y, fmaf(0.2f, fB.y, A5))) : 0.f;
            float e10 = (bb & 1u)   ? ex2f(fmaxf(B1 + fA.x, fmaf(0.2f, fA.x, B5))) : 0.f;
            float e11 = (bb & 2u)   ? ex2f(fmaxf(B1 + fA.y, fmaf(0.2f, fA.y, B5))) : 0.f;
            float e18 = (bb & 256u) ? ex2f(fmaxf(B1 + fB.x, fmaf(0.2f, fB.x, B5))) : 0.f;
            float e19 = (bb & 512u) ? ex2f(fmaxf(B1 + fB.y, fmaf(0.2f, fB.y, B5))) : 0.f;

            const unsigned a0 = packh2(e00, e01);
            const unsigned a1 = packh2(e10, e11);
            const unsigned a2 = packh2(e08, e09);
            const unsigned a3 = packh2(e18, e19);

            // ones-column: accumulates exact row sums of the fp16 P tile
            asm volatile(
                "mma.sync.aligned.m16n8k16.row.col.f32.f16.f16.f32 "
                "{%0,%1,%2,%3}, {%4,%5,%6,%7}, {%8,%9}, {%0,%1,%2,%3};"
                : "+f"(accd[0]), "+f"(accd[1]), "+f"(accd[2]), "+f"(accd[3])
                : "r"(a0), "r"(a1), "r"(a2), "r"(a3), "r"(bones), "r"(bones));

#pragma unroll
            for (int p = 0; p < 4; p++) {
                uint32_t bb0, bb1, bb2, bb3;
                uint32_t addr = ldBase + (uint32_t)((p * 16 * XS_STRIDE + kb) * 2);
                asm volatile("ldmatrix.sync.aligned.m8n8.x4.shared.b16 {%0,%1,%2,%3}, [%4];"
                             : "=r"(bb0), "=r"(bb1), "=r"(bb2), "=r"(bb3) : "r"(addr));
                asm volatile(
                    "mma.sync.aligned.m16n8k16.row.col.f32.f16.f16.f32 "
                    "{%0,%1,%2,%3}, {%4,%5,%6,%7}, {%8,%9}, {%0,%1,%2,%3};"
                    : "+f"(acc[2*p][0]), "+f"(acc[2*p][1]), "+f"(acc[2*p][2]), "+f"(acc[2*p][3])
                    : "r"(a0), "r"(a1), "r"(a2), "r"(a3), "r"(bb0), "r"(bb1));
                asm volatile(
                    "mma.sync.aligned.m16n8k16.row.col.f32.f16.f16.f32 "
                    "{%0,%1,%2,%3}, {%4,%5,%6,%7}, {%8,%9}, {%0,%1,%2,%3};"
                    : "+f"(acc[2*p+1][0]), "+f"(acc[2*p+1][1]), "+f"(acc[2*p+1][2]), "+f"(acc[2*p+1][3])
                    : "r"(a0), "r"(a1), "r"(a2), "r"(a3), "r"(bb2), "r"(bb3));
            }
        }
    }

    const float inv0 = 1.f / accd[0];
    const float inv1 = 1.f / accd[2];

    float* ob0 = out + (size_t)(i0 + r0) * HF + h * FDIM + jb;
    float* ob1 = ob0 + (size_t)8 * HF;
#pragma unroll
    for (int nt = 0; nt < 8; nt++) {
        float2 v0, v1;
        v0.x = eluf(acc[nt][0] * inv0);
        v0.y = eluf(acc[nt][1] * inv0);
        v1.x = eluf(acc[nt][2] * inv1);
        v1.y = eluf(acc[nt][3] * inv1);
        *(float2*)(ob0 + nt * 8) = v0;
        *(float2*)(ob1 + nt * 8) = v1;
    }
}

// ---------------- launch ----------------------------------------------------
extern "C" void kernel_launch(void* const* d_in, const int* in_sizes, int n_in,
                              void* d_out, int out_size) {
    const float* X     = (const float*)d_in[0];
    const int*   A     = (const int*)d_in[1];
    const float* W     = (const float*)d_in[2];
    const float* a_src = (const float*)d_in[3];
    const float* a_dst = (const float*)d_in[4];
    float* out = (float*)d_out;

    pack_a<<<N_NODES, 128>>>(A);
    dim3 ggrid(HF / 64, N_NODES / 128);
    gemm_xw<<<ggrid, 256>>>(X, W);
    dim3 tgrid(HF / 64, N_NODES / 64);
    transpose_xw<<<tgrid, 256>>>(a_src, a_dst);
    agg_mma<<<(N_NODES / 64) * NHEADS, 128>>>(out);
}

// round 6
// speedup vs baseline: 4.8916x; 1.0745x over previous
#include <cuda_runtime.h>
#include <cuda_fp16.h>
#include <cstdint>

#define N_NODES 4096
#define FIN     512
#define NHEADS  4
#define FDIM    64
#define HF      256
#define NW      (N_NODES / 32)   // 128 packed words per A row
#define LOG2E   1.4426950408889634f

// ---------------- device scratch --------------------------------------------
__device__ float    g_XW[(size_t)N_NODES * HF];      // 4 MB  [node][hf] fp32
__device__ __half   g_XWTh[(size_t)HF * N_NODES];    // 2 MB  [hf][node] fp16
__device__ unsigned g_Apack[(size_t)N_NODES * NW];   // 2 MB  bitmask
__device__ float    g_f1[NHEADS * N_NODES];
__device__ float    g_f2[NHEADS * N_NODES];
__device__ int      g_fmax2i[NHEADS];                // monotonic-int encoded max

__device__ __forceinline__ int enc_f(float f) {
    int e = __float_as_int(f);
    return (e >= 0) ? e : (e ^ 0x7FFFFFFF);
}
__device__ __forceinline__ float dec_f(int v) {
    return __int_as_float(v >= 0 ? v : (v ^ 0x7FFFFFFF));
}
__device__ __forceinline__ uint32_t f2tf32(float x) {
    uint32_t u;
    asm("cvt.rna.tf32.f32 %0, %1;" : "=r"(u) : "f"(x));
    return u;
}
__device__ __forceinline__ float ex2f(float x) {
    float r;
    asm("ex2.approx.ftz.f32 %0, %1;" : "=f"(r) : "f"(x));
    return r;
}
__device__ __forceinline__ unsigned packh2(float a, float b) {
    __half2 h = __floats2half2_rn(a, b);
    return *reinterpret_cast<unsigned*>(&h);
}
__device__ __forceinline__ float eluf(float x) { return x > 0.f ? x : (__expf(x) - 1.f); }
__device__ __forceinline__ uint32_t smem_u32(const void* p) {
    uint32_t a;
    asm("{ .reg .u64 t; cvta.to.shared.u64 t, %1; cvt.u32.u64 %0, t; }" : "=r"(a) : "l"(p));
    return a;
}

// ---------------- kernel 0: pack A into bitmask (+ init fmax) ---------------
__global__ void __launch_bounds__(128) pack_a(const int* __restrict__ A) {
    if (blockIdx.x == 0 && threadIdx.x < NHEADS) g_fmax2i[threadIdx.x] = (int)0x80000000;
    const int row = blockIdx.x, w = threadIdx.x >> 5, lane = threadIdx.x & 31;
    const int* ar = A + (size_t)row * N_NODES;
    for (int wi = w; wi < NW; wi += 4) {
        int v = ar[wi * 32 + lane];
        unsigned b = __ballot_sync(0xffffffffu, v != 0);
        if (lane == 0) g_Apack[(size_t)row * NW + wi] = b;
    }
}

// ---------------- kernel 1: XW = X @ W  via tf32 mma.sync -------------------
__global__ void __launch_bounds__(256) gemm_xw(const float* __restrict__ X,
                                               const float* __restrict__ W) {
    __shared__ uint32_t XsT[32][136];
    __shared__ uint32_t Ws[32][72];

    const int t = threadIdx.x, wid = t >> 5, lane = t & 31;
    const int g = lane >> 2, q4 = lane & 3;
    const int bn0 = blockIdx.x * 64;
    const int bm0 = blockIdx.y * 128;
    const int wm = (wid & 3) * 32;
    const int wn = (wid >> 2) * 32;

    float acc[2][4][4];
#pragma unroll
    for (int mt = 0; mt < 2; mt++)
#pragma unroll
        for (int nt = 0; nt < 4; nt++)
#pragma unroll
            for (int k = 0; k < 4; k++) acc[mt][nt][k] = 0.f;

    for (int k0 = 0; k0 < FIN; k0 += 32) {
#pragma unroll
        for (int p = 0; p < 4; p++) {
            int idx = t + p * 256;
            int m = idx & 127, kq = idx >> 7;
            float4 v = *(const float4*)(X + (size_t)(bm0 + m) * FIN + k0 + kq * 4);
            XsT[kq * 4 + 0][m] = f2tf32(v.x);
            XsT[kq * 4 + 1][m] = f2tf32(v.y);
            XsT[kq * 4 + 2][m] = f2tf32(v.z);
            XsT[kq * 4 + 3][m] = f2tf32(v.w);
        }
#pragma unroll
        for (int p = 0; p < 2; p++) {
            int idx = t + p * 256;
            int k = idx >> 4, n4 = idx & 15;
            float4 v = *(const float4*)(W + (size_t)(k0 + k) * HF + bn0 + n4 * 4);
            Ws[k][n4 * 4 + 0] = f2tf32(v.x);
            Ws[k][n4 * 4 + 1] = f2tf32(v.y);
            Ws[k][n4 * 4 + 2] = f2tf32(v.z);
            Ws[k][n4 * 4 + 3] = f2tf32(v.w);
        }
        __syncthreads();

#pragma unroll
        for (int ks = 0; ks < 4; ks++) {
            const int kk = ks * 8;
            uint32_t b0[4], b1[4];
#pragma unroll
            for (int nt = 0; nt < 4; nt++) {
                b0[nt] = Ws[kk + q4][wn + nt * 8 + g];
                b1[nt] = Ws[kk + 4 + q4][wn + nt * 8 + g];
            }
#pragma unroll
            for (int mt = 0; mt < 2; mt++) {
                const int rb = wm + mt * 16;
                uint32_t a0 = XsT[kk + q4][rb + g];
                uint32_t a1 = XsT[kk + q4][rb + g + 8];
                uint32_t a2 = XsT[kk + q4 + 4][rb + g];
                uint32_t a3 = XsT[kk + q4 + 4][rb + g + 8];
#pragma unroll
                for (int nt = 0; nt < 4; nt++) {
                    asm volatile(
                        "mma.sync.aligned.m16n8k8.row.col.f32.tf32.tf32.f32 "
                        "{%0,%1,%2,%3}, {%4,%5,%6,%7}, {%8,%9}, {%0,%1,%2,%3};"
                        : "+f"(acc[mt][nt][0]), "+f"(acc[mt][nt][1]),
                          "+f"(acc[mt][nt][2]), "+f"(acc[mt][nt][3])
                        : "r"(a0), "r"(a1), "r"(a2), "r"(a3), "r"(b0[nt]), "r"(b1[nt]));
                }
            }
        }
        __syncthreads();
    }

#pragma unroll
    for (int mt = 0; mt < 2; mt++) {
        const int r = bm0 + wm + mt * 16 + g;
#pragma unroll
        for (int nt = 0; nt < 4; nt++) {
            const int c = bn0 + wn + nt * 8 + 2 * q4;
            *(float2*)&g_XW[(size_t)r * HF + c]       = make_float2(acc[mt][nt][0], acc[mt][nt][1]);
            *(float2*)&g_XW[(size_t)(r + 8) * HF + c] = make_float2(acc[mt][nt][2], acc[mt][nt][3]);
        }
    }
}

// ---------------- kernel 1b: transpose + f1/f2/fmax (fused) -----------------
__global__ void __launch_bounds__(256) transpose_xw(const float* __restrict__ a_src,
                                                    const float* __restrict__ a_dst) {
    __shared__ float ts[64][65];
    __shared__ float as[64], ad[64];
    __shared__ float f2loc[64];
    const int t = threadIdx.x;
    const int hf0 = blockIdx.x * 64;       // == head h * 64
    const int n0  = blockIdx.y * 64;
    const int h   = blockIdx.x;

    if (t < 64) { as[t] = a_src[hf0 + t]; ad[t] = a_dst[hf0 + t]; }
#pragma unroll
    for (int p = 0; p < 4; p++) {
        int e = t + p * 256;
        int node = e >> 4, c4 = e & 15;
        float4 v = *(const float4*)(g_XW + (size_t)(n0 + node) * HF + hf0 + c4 * 4);
        ts[node][c4 * 4 + 0] = v.x;
        ts[node][c4 * 4 + 1] = v.y;
        ts[node][c4 * 4 + 2] = v.z;
        ts[node][c4 * 4 + 3] = v.w;
    }
    __syncthreads();
#pragma unroll
    for (int p = 0; p < 2; p++) {
        int e = t + p * 256;
        int hf = e >> 3, n8 = e & 7;
        uint4 o;
        unsigned* op = (unsigned*)&o;
#pragma unroll
        for (int i = 0; i < 4; i++)
            op[i] = packh2(ts[n8 * 8 + 2 * i][hf], ts[n8 * 8 + 2 * i + 1][hf]);
        *(uint4*)&g_XWTh[(size_t)(hf0 + hf) * N_NODES + n0 + n8 * 8] = o;
    }
    const int node = t >> 2, q = t & 3;
    float s1 = 0.f, s2 = 0.f;
#pragma unroll
    for (int i = 0; i < 16; i++) {
        float x = ts[node][q * 16 + i];
        s1 += x * as[q * 16 + i];
        s2 += x * ad[q * 16 + i];
    }
    s1 += __shfl_xor_sync(0xffffffffu, s1, 1);
    s1 += __shfl_xor_sync(0xffffffffu, s1, 2);
    s2 += __shfl_xor_sync(0xffffffffu, s2, 1);
    s2 += __shfl_xor_sync(0xffffffffu, s2, 2);
    if (q == 0) {
        float f2v = s2 * LOG2E;
        g_f1[h * N_NODES + n0 + node] = s1 * LOG2E;
        g_f2[h * N_NODES + n0 + node] = f2v;
        f2loc[node] = f2v;
    }
    __syncthreads();
    if (t < 32) {
        float m = fmaxf(f2loc[t], f2loc[t + 32]);
#pragma unroll
        for (int o = 16; o > 0; o >>= 1)
            m = fmaxf(m, __shfl_xor_sync(0xffffffffu, m, o));
        if (t == 0) atomicMax(&g_fmax2i[h], enc_f(m));
    }
}

// ---------------- kernel 4: HMMA aggregation, 8 warps, j-split --------------
// CTA = (64-row i-tile, head); 2 warp-groups over disjoint j-chunks; each warp
// owns a 16x64 output tile. Double-buffered XW^T tiles; combine at end.
#define KC 128
#define XS_STRIDE 136   // halves; 272 B row -> ldmatrix conflict-free

__global__ void __launch_bounds__(256, 2) agg_mma(float* __restrict__ out) {
    __shared__ __align__(16) __half xs[2][64][XS_STRIDE];  // 34.8 KB
    __shared__ __align__(16) float f2s[2][KC];

    const int t = threadIdx.x;
    const int grp = t >> 7;            // j-group 0/1
    const int tl  = t & 127;
    const int wid = tl >> 5, lane = t & 31;
    const int h  = blockIdx.x & 3;
    const int i0 = (blockIdx.x >> 2) << 6;
    const int g  = lane >> 2;
    const int q4 = lane & 3;
    const int jb = q4 * 2;
    const int r0 = wid * 16 + g;

    const float fm  = dec_f(g_fmax2i[h]);
    const float f1a = g_f1[h * N_NODES + i0 + r0];
    const float f1b = g_f1[h * N_NODES + i0 + r0 + 8];
    const float ma = fmaxf(f1a + fm, 0.2f * (f1a + fm));
    const float mb = fmaxf(f1b + fm, 0.2f * (f1b + fm));
    const float A1 = f1a - ma, A5 = 0.2f * f1a - ma;
    const float B1 = f1b - mb, B5 = 0.2f * f1b - mb;

    const float*    f2base = g_f2 + h * N_NODES;
    const unsigned* apA = g_Apack + (size_t)(i0 + r0) * NW;
    const unsigned* apB = apA + (size_t)8 * NW;
    const __half*   xwt = g_XWTh + (size_t)h * FDIM * N_NODES;

    const int ldrow = lane & 7, msel = lane >> 3;
    const uint32_t xsb = smem_u32(&xs[grp][0][0]);
    const uint32_t ldBase = xsb + (uint32_t)((((msel >> 1) * 8 + ldrow) * XS_STRIDE + (msel & 1) * 8) * 2);

    float acc[8][4];
#pragma unroll
    for (int nt = 0; nt < 8; nt++)
#pragma unroll
        for (int k = 0; k < 4; k++) acc[nt][k] = 0.f;
    float accd[4] = {0.f, 0.f, 0.f, 0.f};
    const unsigned bones = 0x3C003C00u;

    for (int it = 0; it < N_NODES / (2 * KC); it++) {
        __syncthreads();
        // cooperative staging of BOTH tiles (chunks 2*it and 2*it+1)
#pragma unroll
        for (int q = 0; q < 8; q++) {
            int e = t + q * 256;
            int tile = e >> 10, wi = e & 1023;
            int f = wi >> 4, cc = wi & 15;
            *(uint4*)&xs[tile][f][cc * 8] =
                *(const uint4*)(xwt + (size_t)f * N_NODES + (2 * it + tile) * KC + cc * 8);
        }
        if (t < 64) {
            int buf = t >> 5, i4 = t & 31;
            ((float4*)f2s[buf])[i4] = ((const float4*)(f2base + (2 * it + buf) * KC))[i4];
        }
        __syncthreads();

        const int j0 = (2 * it + grp) * KC;
        uint4 mua = *(const uint4*)&apA[j0 >> 5];
        uint4 mub = *(const uint4*)&apB[j0 >> 5];
        unsigned mwa[4] = {mua.x, mua.y, mua.z, mua.w};
        unsigned mwb[4] = {mub.x, mub.y, mub.z, mub.w};

#pragma unroll
        for (int ks = 0; ks < 8; ks++) {
            const int kb = ks * 16;
            const float2 fA = *(const float2*)&f2s[grp][kb + jb];
            const float2 fB = *(const float2*)&f2s[grp][kb + jb + 8];
            const unsigned ba = mwa[ks >> 1] >> ((ks & 1) * 16 + jb);
            const unsigned bb = mwb[ks >> 1] >> ((ks & 1) * 16 + jb);

            float e00 = (ba & 1u)   ? ex2f(fmaxf(A1 + fA.x, fmaf(0.2f, fA.x, A5))) : 0.f;
            float e01 = (ba & 2u)   ? ex2f(fmaxf(A1 + fA.y, fmaf(0.2f, fA.y, A5))) : 0.f;
            float e08 = (ba & 256u) ? ex2f(fmaxf(A1 + fB.x, fmaf(0.2f, fB.x, A5))) : 0.f;
            float e09 = (ba & 512u) ? ex2f(fmaxf(A1 + fB.y, fmaf(0.2f, fB.y, A5))) : 0.f;
            float e10 = (bb & 1u)   ? ex2f(fmaxf(B1 + fA.x, fmaf(0.2f, fA.x, B5))) : 0.f;
            float e11 = (bb & 2u)   ? ex2f(fmaxf(B1 + fA.y, fmaf(0.2f, fA.y, B5))) : 0.f;
            float e18 = (bb & 256u) ? ex2f(fmaxf(B1 + fB.x, fmaf(0.2f, fB.x, B5))) : 0.f;
            float e19 = (bb & 512u) ? ex2f(fmaxf(B1 + fB.y, fmaf(0.2f, fB.y, B5))) : 0.f;

            const unsigned a0 = packh2(e00, e01);
            const unsigned a1 = packh2(e10, e11);
            const unsigned a2 = packh2(e08, e09);
            const unsigned a3 = packh2(e18, e19);

            asm volatile(
                "mma.sync.aligned.m16n8k16.row.col.f32.f16.f16.f32 "
                "{%0,%1,%2,%3}, {%4,%5,%6,%7}, {%8,%9}, {%0,%1,%2,%3};"
                : "+f"(accd[0]), "+f"(accd[1]), "+f"(accd[2]), "+f"(accd[3])
                : "r"(a0), "r"(a1), "r"(a2), "r"(a3), "r"(bones), "r"(bones));

#pragma unroll
            for (int p = 0; p < 4; p++) {
                uint32_t bb0, bb1, bb2, bb3;
                uint32_t addr = ldBase + (uint32_t)((p * 16 * XS_STRIDE + kb) * 2);
                asm volatile("ldmatrix.sync.aligned.m8n8.x4.shared.b16 {%0,%1,%2,%3}, [%4];"
                             : "=r"(bb0), "=r"(bb1), "=r"(bb2), "=r"(bb3) : "r"(addr));
                asm volatile(
                    "mma.sync.aligned.m16n8k16.row.col.f32.f16.f16.f32 "
                    "{%0,%1,%2,%3}, {%4,%5,%6,%7}, {%8,%9}, {%0,%1,%2,%3};"
                    : "+f"(acc[2*p][0]), "+f"(acc[2*p][1]), "+f"(acc[2*p][2]), "+f"(acc[2*p][3])
                    : "r"(a0), "r"(a1), "r"(a2), "r"(a3), "r"(bb0), "r"(bb1));
                asm volatile(
                    "mma.sync.aligned.m16n8k16.row.col.f32.f16.f16.f32 "
                    "{%0,%1,%2,%3}, {%4,%5,%6,%7}, {%8,%9}, {%0,%1,%2,%3};"
                    : "+f"(acc[2*p+1][0]), "+f"(acc[2*p+1][1]), "+f"(acc[2*p+1][2]), "+f"(acc[2*p+1][3])
                    : "r"(a0), "r"(a1), "r"(a2), "r"(a3), "r"(bb2), "r"(bb3));
            }
        }
    }

    // ---- combine group 1 into group 0 via (dead) xs storage -----------------
    float* red = (float*)&xs[0][0][0];   // 34 rows x 128 floats = 17.4 KB
    __syncthreads();
    if (grp == 1) {
#pragma unroll
        for (int nt = 0; nt < 8; nt++)
#pragma unroll
            for (int k = 0; k < 4; k++)
                red[(nt * 4 + k) * 128 + tl] = acc[nt][k];
        red[32 * 128 + tl] = accd[0];
        red[33 * 128 + tl] = accd[2];
    }
    __syncthreads();
    if (grp == 0) {
#pragma unroll
        for (int nt = 0; nt < 8; nt++)
#pragma unroll
            for (int k = 0; k < 4; k++)
                acc[nt][k] += red[(nt * 4 + k) * 128 + tl];
        accd[0] += red[32 * 128 + tl];
        accd[2] += red[33 * 128 + tl];

        const float inv0 = 1.f / accd[0];
        const float inv1 = 1.f / accd[2];
        float* ob0 = out + (size_t)(i0 + r0) * HF + h * FDIM + jb;
        float* ob1 = ob0 + (size_t)8 * HF;
#pragma unroll
        for (int nt = 0; nt < 8; nt++) {
            float2 v0, v1;
            v0.x = eluf(acc[nt][0] * inv0);
            v0.y = eluf(acc[nt][1] * inv0);
            v1.x = eluf(acc[nt][2] * inv1);
            v1.y = eluf(acc[nt][3] * inv1);
            *(float2*)(ob0 + nt * 8) = v0;
            *(float2*)(ob1 + nt * 8) = v1;
        }
    }
}

// ---------------- launch ----------------------------------------------------
extern "C" void kernel_launch(void* const* d_in, const int* in_sizes, int n_in,
                              void* d_out, int out_size) {
    const float* X     = (const float*)d_in[0];
    const int*   A     = (const int*)d_in[1];
    const float* W     = (const float*)d_in[2];
    const float* a_src = (const float*)d_in[3];
    const float* a_dst = (const float*)d_in[4];
    float* out = (float*)d_out;

    pack_a<<<N_NODES, 128>>>(A);
    dim3 ggrid(HF / 64, N_NODES / 128);
    gemm_xw<<<ggrid, 256>>>(X, W);
    dim3 tgrid(HF / 64, N_NODES / 64);
    transpose_xw<<<tgrid, 256>>>(a_src, a_dst);
    agg_mma<<<(N_NODES / 64) * NHEADS, 256>>>(out);
}

// round 7
// speedup vs baseline: 5.0270x; 1.0277x over previous
#include <cuda_runtime.h>
#include <cuda_fp16.h>
#include <cstdint>

#define N_NODES 4096
#define FIN     512
#define NHEADS  4
#define FDIM    64
#define HF      256
#define LOG2E   1.4426950408889634f

// ---------------- device scratch --------------------------------------------
__device__ float    g_XW[(size_t)N_NODES * HF];        // 4 MB  [node][hf] fp32
__device__ __half   g_XWTh[(size_t)HF * N_NODES];      // 2 MB  [hf][node] fp16
__device__ unsigned g_Apack2[(size_t)N_NODES * 32 * 4];// 2 MB  repacked bitmask
__device__ float    g_f1[NHEADS * N_NODES];
__device__ __half   g_f2h[NHEADS * N_NODES];           // fp16 dst scores
__device__ int      g_fmax2i[NHEADS];

__device__ __forceinline__ int enc_f(float f) {
    int e = __float_as_int(f);
    return (e >= 0) ? e : (e ^ 0x7FFFFFFF);
}
__device__ __forceinline__ float dec_f(int v) {
    return __int_as_float(v >= 0 ? v : (v ^ 0x7FFFFFFF));
}
__device__ __forceinline__ uint32_t f2tf32(float x) {
    uint32_t u;
    asm("cvt.rna.tf32.f32 %0, %1;" : "=r"(u) : "f"(x));
    return u;
}
__device__ __forceinline__ unsigned ex2h2(unsigned x) {
    unsigned r;
    asm("ex2.approx.f16x2 %0, %1;" : "=r"(r) : "r"(x));
    return r;
}
__device__ __forceinline__ unsigned prmt(unsigned a, unsigned sel) {
    unsigned r;
    asm("prmt.b32 %0, %1, %1, %2;" : "=r"(r) : "r"(a), "r"(sel));
    return r;
}
__device__ __forceinline__ unsigned packh2(float a, float b) {
    __half2 h = __floats2half2_rn(a, b);
    return *reinterpret_cast<unsigned*>(&h);
}
__device__ __forceinline__ float eluf(float x) { return x > 0.f ? x : (__expf(x) - 1.f); }
__device__ __forceinline__ uint32_t smem_u32(const void* p) {
    uint32_t a;
    asm("{ .reg .u64 t; cvta.to.shared.u64 t, %1; cvt.u32.u64 %0, t; }" : "=r"(a) : "l"(p));
    return a;
}

// ---------------- kernel 0: repack A -----------------------------------------
// word (row, c, q4): bit (e*8+ks) = A[row][c*128 + ks*16 + 2*q4 + (e&1) + 8*(e>>1)]
__global__ void __launch_bounds__(128) pack_a(const int* __restrict__ A) {
    if (blockIdx.x == 0 && threadIdx.x < NHEADS) g_fmax2i[threadIdx.x] = (int)0x80000000;
    const int row = blockIdx.x;
    const int w = threadIdx.x >> 5, lane = threadIdx.x & 31;
    const int e = lane >> 3, ks = lane & 7;
    const int eoff = (e & 1) + ((e & 2) ? 8 : 0) + ks * 16;
    const int* ar = A + (size_t)row * N_NODES;
#pragma unroll 4
    for (int i = 0; i < 32; i++) {
        int wi = w * 32 + i;
        int c = wi >> 2, q4 = wi & 3;
        int v = ar[c * 128 + 2 * q4 + eoff];
        unsigned b = __ballot_sync(0xffffffffu, v != 0);
        if (lane == 0) g_Apack2[((size_t)row * 32 + c) * 4 + q4] = b;
    }
}

// ---------------- kernel 1: XW = X @ W  via tf32 mma.sync -------------------
__global__ void __launch_bounds__(256) gemm_xw(const float* __restrict__ X,
                                               const float* __restrict__ W) {
    __shared__ uint32_t XsT[32][136];
    __shared__ uint32_t Ws[32][72];

    const int t = threadIdx.x, wid = t >> 5, lane = t & 31;
    const int g = lane >> 2, q4 = lane & 3;
    const int bn0 = blockIdx.x * 64;
    const int bm0 = blockIdx.y * 128;
    const int wm = (wid & 3) * 32;
    const int wn = (wid >> 2) * 32;

    float acc[2][4][4];
#pragma unroll
    for (int mt = 0; mt < 2; mt++)
#pragma unroll
        for (int nt = 0; nt < 4; nt++)
#pragma unroll
            for (int k = 0; k < 4; k++) acc[mt][nt][k] = 0.f;

    for (int k0 = 0; k0 < FIN; k0 += 32) {
#pragma unroll
        for (int p = 0; p < 4; p++) {
            int idx = t + p * 256;
            int m = idx & 127, kq = idx >> 7;
            float4 v = *(const float4*)(X + (size_t)(bm0 + m) * FIN + k0 + kq * 4);
            XsT[kq * 4 + 0][m] = f2tf32(v.x);
            XsT[kq * 4 + 1][m] = f2tf32(v.y);
            XsT[kq * 4 + 2][m] = f2tf32(v.z);
            XsT[kq * 4 + 3][m] = f2tf32(v.w);
        }
#pragma unroll
        for (int p = 0; p < 2; p++) {
            int idx = t + p * 256;
            int k = idx >> 4, n4 = idx & 15;
            float4 v = *(const float4*)(W + (size_t)(k0 + k) * HF + bn0 + n4 * 4);
            Ws[k][n4 * 4 + 0] = f2tf32(v.x);
            Ws[k][n4 * 4 + 1] = f2tf32(v.y);
            Ws[k][n4 * 4 + 2] = f2tf32(v.z);
            Ws[k][n4 * 4 + 3] = f2tf32(v.w);
        }
        __syncthreads();

#pragma unroll
        for (int ks = 0; ks < 4; ks++) {
            const int kk = ks * 8;
            uint32_t b0[4], b1[4];
#pragma unroll
            for (int nt = 0; nt < 4; nt++) {
                b0[nt] = Ws[kk + q4][wn + nt * 8 + g];
                b1[nt] = Ws[kk + 4 + q4][wn + nt * 8 + g];
            }
#pragma unroll
            for (int mt = 0; mt < 2; mt++) {
                const int rb = wm + mt * 16;
                uint32_t a0 = XsT[kk + q4][rb + g];
                uint32_t a1 = XsT[kk + q4][rb + g + 8];
                uint32_t a2 = XsT[kk + q4 + 4][rb + g];
                uint32_t a3 = XsT[kk + q4 + 4][rb + g + 8];
#pragma unroll
                for (int nt = 0; nt < 4; nt++) {
                    asm volatile(
                        "mma.sync.aligned.m16n8k8.row.col.f32.tf32.tf32.f32 "
                        "{%0,%1,%2,%3}, {%4,%5,%6,%7}, {%8,%9}, {%0,%1,%2,%3};"
                        : "+f"(acc[mt][nt][0]), "+f"(acc[mt][nt][1]),
                          "+f"(acc[mt][nt][2]), "+f"(acc[mt][nt][3])
                        : "r"(a0), "r"(a1), "r"(a2), "r"(a3), "r"(b0[nt]), "r"(b1[nt]));
                }
            }
        }
        __syncthreads();
    }

#pragma unroll
    for (int mt = 0; mt < 2; mt++) {
        const int r = bm0 + wm + mt * 16 + g;
#pragma unroll
        for (int nt = 0; nt < 4; nt++) {
            const int c = bn0 + wn + nt * 8 + 2 * q4;
            *(float2*)&g_XW[(size_t)r * HF + c]       = make_float2(acc[mt][nt][0], acc[mt][nt][1]);
            *(float2*)&g_XW[(size_t)(r + 8) * HF + c] = make_float2(acc[mt][nt][2], acc[mt][nt][3]);
        }
    }
}

// ---------------- kernel 1b: transpose + f1/f2h/fmax (fused) ----------------
__global__ void __launch_bounds__(256) transpose_xw(const float* __restrict__ a_src,
                                                    const float* __restrict__ a_dst) {
    __shared__ float ts[64][65];
    __shared__ float as[64], ad[64];
    __shared__ float f2loc[64];
    const int t = threadIdx.x;
    const int hf0 = blockIdx.x * 64;       // == head h * 64
    const int n0  = blockIdx.y * 64;
    const int h   = blockIdx.x;

    if (t < 64) { as[t] = a_src[hf0 + t]; ad[t] = a_dst[hf0 + t]; }
#pragma unroll
    for (int p = 0; p < 4; p++) {
        int e = t + p * 256;
        int node = e >> 4, c4 = e & 15;
        float4 v = *(const float4*)(g_XW + (size_t)(n0 + node) * HF + hf0 + c4 * 4);
        ts[node][c4 * 4 + 0] = v.x;
        ts[node][c4 * 4 + 1] = v.y;
        ts[node][c4 * 4 + 2] = v.z;
        ts[node][c4 * 4 + 3] = v.w;
    }
    __syncthreads();
#pragma unroll
    for (int p = 0; p < 2; p++) {
        int e = t + p * 256;
        int hf = e >> 3, n8 = e & 7;
        uint4 o;
        unsigned* op = (unsigned*)&o;
#pragma unroll
        for (int i = 0; i < 4; i++)
            op[i] = packh2(ts[n8 * 8 + 2 * i][hf], ts[n8 * 8 + 2 * i + 1][hf]);
        *(uint4*)&g_XWTh[(size_t)(hf0 + hf) * N_NODES + n0 + n8 * 8] = o;
    }
    const int node = t >> 2, q = t & 3;
    float s1 = 0.f, s2 = 0.f;
#pragma unroll
    for (int i = 0; i < 16; i++) {
        float x = ts[node][q * 16 + i];
        s1 += x * as[q * 16 + i];
        s2 += x * ad[q * 16 + i];
    }
    s1 += __shfl_xor_sync(0xffffffffu, s1, 1);
    s1 += __shfl_xor_sync(0xffffffffu, s1, 2);
    s2 += __shfl_xor_sync(0xffffffffu, s2, 1);
    s2 += __shfl_xor_sync(0xffffffffu, s2, 2);
    if (q == 0) {
        float f2v = s2 * LOG2E;
        g_f1[h * N_NODES + n0 + node] = s1 * LOG2E;
        g_f2h[h * N_NODES + n0 + node] = __float2half_rn(f2v);
        f2loc[node] = f2v;
    }
    __syncthreads();
    if (t < 32) {
        float m = fmaxf(f2loc[t], f2loc[t + 32]);
#pragma unroll
        for (int o = 16; o > 0; o >>= 1)
            m = fmaxf(m, __shfl_xor_sync(0xffffffffu, m, o));
        if (t == 0) atomicMax(&g_fmax2i[h], enc_f(m));
    }
}

// ---------------- kernel 4: HMMA aggregation, fp16x2 score pipeline ---------
#define KC 128
#define XS_STRIDE 136   // halves; 272 B row -> ldmatrix conflict-free

__global__ void __launch_bounds__(256, 2) agg_mma(float* __restrict__ out) {
    __shared__ __align__(16) __half xs[2][64][XS_STRIDE];  // 34.8 KB
    __shared__ __align__(16) __half2 f2s[2][KC / 2];       // 512 B

    const int t = threadIdx.x;
    const int grp = t >> 7;            // j-group 0/1
    const int tl  = t & 127;
    const int wid = tl >> 5, lane = t & 31;
    const int h  = blockIdx.x & 3;
    const int i0 = (blockIdx.x >> 2) << 6;
    const int g  = lane >> 2;
    const int q4 = lane & 3;
    const int jb = q4 * 2;
    const int r0 = wid * 16 + g;

    const float fm  = dec_f(g_fmax2i[h]);
    const float f1a = g_f1[h * N_NODES + i0 + r0];
    const float f1b = g_f1[h * N_NODES + i0 + r0 + 8];
    const float ma = fmaxf(f1a + fm, 0.2f * (f1a + fm));
    const float mb = fmaxf(f1b + fm, 0.2f * (f1b + fm));
    // folded row constants (cancel in softmax normalization; fp16 is safe)
    const __half2 A1 = __half2half2(__float2half_rn(f1a - ma));
    const __half2 A5 = __half2half2(__float2half_rn(0.2f * f1a - ma));
    const __half2 B1 = __half2half2(__float2half_rn(f1b - mb));
    const __half2 B5 = __half2half2(__float2half_rn(0.2f * f1b - mb));
    const __half2 C02 = __half2half2(__float2half_rn(0.2f));

    const __half*    f2hbase = g_f2h + h * N_NODES;
    const unsigned*  apA = g_Apack2 + ((size_t)(i0 + r0) * 32) * 4 + q4;
    const unsigned*  apB = apA + (size_t)8 * 32 * 4;
    const __half*    xwt = g_XWTh + (size_t)h * FDIM * N_NODES;

    const int ldrow = lane & 7, msel = lane >> 3;
    const uint32_t xsb = smem_u32(&xs[grp][0][0]);
    const uint32_t ldBase = xsb + (uint32_t)((((msel >> 1) * 8 + ldrow) * XS_STRIDE + (msel & 1) * 8) * 2);

    float acc[8][4];
#pragma unroll
    for (int nt = 0; nt < 8; nt++)
#pragma unroll
        for (int k = 0; k < 4; k++) acc[nt][k] = 0.f;
    float accd[4] = {0.f, 0.f, 0.f, 0.f};
    const unsigned bones = 0x3C003C00u;

    for (int it = 0; it < N_NODES / (2 * KC); it++) {
        __syncthreads();
        // cooperative staging of BOTH XW^T tiles (chunks 2*it, 2*it+1)
#pragma unroll
        for (int q = 0; q < 8; q++) {
            int e = t + q * 256;
            int tile = e >> 10, wi = e & 1023;
            int f = wi >> 4, cc = wi & 15;
            *(uint4*)&xs[tile][f][cc * 8] =
                *(const uint4*)(xwt + (size_t)f * N_NODES + (2 * it + tile) * KC + cc * 8);
        }
        if (t < 32)   // 512 B of fp16 f2 for both chunks
            ((uint4*)&f2s[0][0])[t] = ((const uint4*)(f2hbase + 2 * it * KC))[t];
        __syncthreads();

        const int cidx = 2 * it + grp;
        const unsigned wa = apA[cidx * 4];
        const unsigned wb = apB[cidx * 4];

#pragma unroll
        for (int ks = 0; ks < 8; ks++) {
            const int kb = ks * 16;
            const __half2 f01 = f2s[grp][(kb + jb) >> 1];
            const __half2 f89 = f2s[grp][(kb + jb + 8) >> 1];

            // masks via PRMT sign-replication
            const unsigned ra = wa << (7 - ks);
            const unsigned rb = wb << (7 - ks);
            const unsigned mka01 = prmt(ra, 0x9988u);
            const unsigned mka89 = prmt(ra, 0xBBAAu);
            const unsigned mkb01 = prmt(rb, 0x9988u);
            const unsigned mkb89 = prmt(rb, 0xBBAAu);

            // fp16x2 scores + exp (results are HMMA A-fragments directly)
            __half2 sa01 = __hmax2(__hadd2(A1, f01), __hfma2(C02, f01, A5));
            __half2 sa89 = __hmax2(__hadd2(A1, f89), __hfma2(C02, f89, A5));
            __half2 sb01 = __hmax2(__hadd2(B1, f01), __hfma2(C02, f01, B5));
            __half2 sb89 = __hmax2(__hadd2(B1, f89), __hfma2(C02, f89, B5));
            const unsigned a0 = ex2h2(*(unsigned*)&sa01) & mka01;
            const unsigned a1 = ex2h2(*(unsigned*)&sb01) & mkb01;
            const unsigned a2 = ex2h2(*(unsigned*)&sa89) & mka89;
            const unsigned a3 = ex2h2(*(unsigned*)&sb89) & mkb89;

            // ones-column: exact row sums of the fp16 P tile
            asm volatile(
                "mma.sync.aligned.m16n8k16.row.col.f32.f16.f16.f32 "
                "{%0,%1,%2,%3}, {%4,%5,%6,%7}, {%8,%9}, {%0,%1,%2,%3};"
                : "+f"(accd[0]), "+f"(accd[1]), "+f"(accd[2]), "+f"(accd[3])
                : "r"(a0), "r"(a1), "r"(a2), "r"(a3), "r"(bones), "r"(bones));

#pragma unroll
            for (int p = 0; p < 4; p++) {
                uint32_t bb0, bb1, bb2, bb3;
                uint32_t addr = ldBase + (uint32_t)((p * 16 * XS_STRIDE + kb) * 2);
                asm volatile("ldmatrix.sync.aligned.m8n8.x4.shared.b16 {%0,%1,%2,%3}, [%4];"
                             : "=r"(bb0), "=r"(bb1), "=r"(bb2), "=r"(bb3) : "r"(addr));
                asm volatile(
                    "mma.sync.aligned.m16n8k16.row.col.f32.f16.f16.f32 "
                    "{%0,%1,%2,%3}, {%4,%5,%6,%7}, {%8,%9}, {%0,%1,%2,%3};"
                    : "+f"(acc[2*p][0]), "+f"(acc[2*p][1]), "+f"(acc[2*p][2]), "+f"(acc[2*p][3])
                    : "r"(a0), "r"(a1), "r"(a2), "r"(a3), "r"(bb0), "r"(bb1));
                asm volatile(
                    "mma.sync.aligned.m16n8k16.row.col.f32.f16.f16.f32 "
                    "{%0,%1,%2,%3}, {%4,%5,%6,%7}, {%8,%9}, {%0,%1,%2,%3};"
                    : "+f"(acc[2*p+1][0]), "+f"(acc[2*p+1][1]), "+f"(acc[2*p+1][2]), "+f"(acc[2*p+1][3])
                    : "r"(a0), "r"(a1), "r"(a2), "r"(a3), "r"(bb2), "r"(bb3));
            }
        }
    }

    // ---- combine group 1 into group 0 via (dead) xs storage -----------------
    float* red = (float*)&xs[0][0][0];
    __syncthreads();
    if (grp == 1) {
#pragma unroll
        for (int nt = 0; nt < 8; nt++)
#pragma unroll
            for (int k = 0; k < 4; k++)
                red[(nt * 4 + k) * 128 + tl] = acc[nt][k];
        red[32 * 128 + tl] = accd[0];
        red[33 * 128 + tl] = accd[2];
    }
    __syncthreads();
    if (grp == 0) {
#pragma unroll
        for (int nt = 0; nt < 8; nt++)
#pragma unroll
            for (int k = 0; k < 4; k++)
                acc[nt][k] += red[(nt * 4 + k) * 128 + tl];
        accd[0] += red[32 * 128 + tl];
        accd[2] += red[33 * 128 + tl];

        const float inv0 = 1.f / accd[0];
        const float inv1 = 1.f / accd[2];
        float* ob0 = out + (size_t)(i0 + r0) * HF + h * FDIM + jb;
        float* ob1 = ob0 + (size_t)8 * HF;
#pragma unroll
        for (int nt = 0; nt < 8; nt++) {
            float2 v0, v1;
            v0.x = eluf(acc[nt][0] * inv0);
            v0.y = eluf(acc[nt][1] * inv0);
            v1.x = eluf(acc[nt][2] * inv1);
            v1.y = eluf(acc[nt][3] * inv1);
            *(float2*)(ob0 + nt * 8) = v0;
            *(float2*)(ob1 + nt * 8) = v1;
        }
    }
}

// ---------------- launch ----------------------------------------------------
extern "C" void kernel_launch(void* const* d_in, const int* in_sizes, int n_in,
                              void* d_out, int out_size) {
    const float* X     = (const float*)d_in[0];
    const int*   A     = (const int*)d_in[1];
    const float* W     = (const float*)d_in[2];
    const float* a_src = (const float*)d_in[3];
    const float* a_dst = (const float*)d_in[4];
    float* out = (float*)d_out;

    pack_a<<<N_NODES, 128>>>(A);
    dim3 ggrid(HF / 64, N_NODES / 128);
    gemm_xw<<<ggrid, 256>>>(X, W);
    dim3 tgrid(HF / 64, N_NODES / 64);
    transpose_xw<<<tgrid, 256>>>(a_src, a_dst);
    agg_mma<<<(N_NODES / 64) * NHEADS, 256>>>(out);
}

// round 10
// speedup vs baseline: 5.1035x; 1.0152x over previous
#include <cuda_runtime.h>
#include <cuda_fp16.h>
#include <cstdint>

#define N_NODES 4096
#define FIN     512
#define NHEADS  4
#define FDIM    64
#define HF      256
#define LOG2E   1.4426950408889634f

// ---------------- device scratch --------------------------------------------
__device__ float    g_XW[(size_t)N_NODES * HF];        // 4 MB  [node][hf] fp32
__device__ __half   g_XWTh[(size_t)HF * N_NODES];      // 2 MB  [hf][node] fp16
__device__ unsigned g_Apack2[(size_t)N_NODES * 32 * 4];// 2 MB  repacked bitmask
__device__ float    g_f1[NHEADS * N_NODES];
__device__ __half   g_f2h[NHEADS * N_NODES];           // fp16 dst scores
__device__ int      g_fmax2i[NHEADS];

__device__ __forceinline__ int enc_f(float f) {
    int e = __float_as_int(f);
    return (e >= 0) ? e : (e ^ 0x7FFFFFFF);
}
__device__ __forceinline__ float dec_f(int v) {
    return __int_as_float(v >= 0 ? v : (v ^ 0x7FFFFFFF));
}
__device__ __forceinline__ uint32_t f2tf32(float x) {
    uint32_t u;
    asm("cvt.rna.tf32.f32 %0, %1;" : "=r"(u) : "f"(x));
    return u;
}
__device__ __forceinline__ unsigned ex2h2(unsigned x) {
    unsigned r;
    asm("ex2.approx.f16x2 %0, %1;" : "=r"(r) : "r"(x));
    return r;
}
__device__ __forceinline__ unsigned prmt(unsigned a, unsigned sel) {
    unsigned r;
    asm("prmt.b32 %0, %1, %1, %2;" : "=r"(r) : "r"(a), "r"(sel));
    return r;
}
__device__ __forceinline__ unsigned packh2(float a, float b) {
    __half2 h = __floats2half2_rn(a, b);
    return *reinterpret_cast<unsigned*>(&h);
}
__device__ __forceinline__ float eluf(float x) { return x > 0.f ? x : (__expf(x) - 1.f); }
__device__ __forceinline__ uint32_t smem_u32(const void* p) {
    uint32_t a;
    asm("{ .reg .u64 t; cvta.to.shared.u64 t, %1; cvt.u32.u64 %0, t; }" : "=r"(a) : "l"(p));
    return a;
}
#define CP_ASYNC16(dst, src) \
    asm volatile("cp.async.cg.shared.global [%0], [%1], 16;" :: "r"(dst), "l"(src))
#define CP_COMMIT() asm volatile("cp.async.commit_group;" ::: "memory")
#define CP_WAIT1()  asm volatile("cp.async.wait_group 1;" ::: "memory")
#define CP_WAIT0()  asm volatile("cp.async.wait_group 0;" ::: "memory")

// ---------------- kernel 0: repack A -----------------------------------------
// word (row, c, q4): bit (e*8+ks) = A[row][c*128 + ks*16 + 2*q4 + (e&1) + 8*(e>>1)]
__global__ void __launch_bounds__(128) pack_a(const int* __restrict__ A) {
    if (blockIdx.x == 0 && threadIdx.x < NHEADS) g_fmax2i[threadIdx.x] = (int)0x80000000;
    const int row = blockIdx.x;
    const int w = threadIdx.x >> 5, lane = threadIdx.x & 31;
    const int e = lane >> 3, ks = lane & 7;
    const int eoff = (e & 1) + ((e & 2) ? 8 : 0) + ks * 16;
    const int* ar = A + (size_t)row * N_NODES;
#pragma unroll 4
    for (int i = 0; i < 32; i++) {
        int wi = w * 32 + i;
        int c = wi >> 2, q4 = wi & 3;
        int v = ar[c * 128 + 2 * q4 + eoff];
        unsigned b = __ballot_sync(0xffffffffu, v != 0);
        if (lane == 0) g_Apack2[((size_t)row * 32 + c) * 4 + q4] = b;
    }
}

// ---------------- kernel 1: XW = X @ W  via tf32 mma.sync -------------------
__global__ void __launch_bounds__(256) gemm_xw(const float* __restrict__ X,
                                               const float* __restrict__ W) {
    __shared__ uint32_t XsT[32][136];
    __shared__ uint32_t Ws[32][72];

    const int t = threadIdx.x, wid = t >> 5, lane = t & 31;
    const int g = lane >> 2, q4 = lane & 3;
    const int bn0 = blockIdx.x * 64;
    const int bm0 = blockIdx.y * 128;
    const int wm = (wid & 3) * 32;
    const int wn = (wid >> 2) * 32;

    float acc[2][4][4];
#pragma unroll
    for (int mt = 0; mt < 2; mt++)
#pragma unroll
        for (int nt = 0; nt < 4; nt++)
#pragma unroll
            for (int k = 0; k < 4; k++) acc[mt][nt][k] = 0.f;

    for (int k0 = 0; k0 < FIN; k0 += 32) {
#pragma unroll
        for (int p = 0; p < 4; p++) {
            int idx = t + p * 256;
            int m = idx & 127, kq = idx >> 7;
            float4 v = *(const float4*)(X + (size_t)(bm0 + m) * FIN + k0 + kq * 4);
            XsT[kq * 4 + 0][m] = f2tf32(v.x);
            XsT[kq * 4 + 1][m] = f2tf32(v.y);
            XsT[kq * 4 + 2][m] = f2tf32(v.z);
            XsT[kq * 4 + 3][m] = f2tf32(v.w);
        }
#pragma unroll
        for (int p = 0; p < 2; p++) {
            int idx = t + p * 256;
            int k = idx >> 4, n4 = idx & 15;
            float4 v = *(const float4*)(W + (size_t)(k0 + k) * HF + bn0 + n4 * 4);
            Ws[k][n4 * 4 + 0] = f2tf32(v.x);
            Ws[k][n4 * 4 + 1] = f2tf32(v.y);
            Ws[k][n4 * 4 + 2] = f2tf32(v.z);
            Ws[k][n4 * 4 + 3] = f2tf32(v.w);
        }
        __syncthreads();

#pragma unroll
        for (int ks = 0; ks < 4; ks++) {
            const int kk = ks * 8;
            uint32_t b0[4], b1[4];
#pragma unroll
            for (int nt = 0; nt < 4; nt++) {
                b0[nt] = Ws[kk + q4][wn + nt * 8 + g];
                b1[nt] = Ws[kk + 4 + q4][wn + nt * 8 + g];
            }
#pragma unroll
            for (int mt = 0; mt < 2; mt++) {
                const int rb = wm + mt * 16;
                uint32_t a0 = XsT[kk + q4][rb + g];
                uint32_t a1 = XsT[kk + q4][rb + g + 8];
                uint32_t a2 = XsT[kk + q4 + 4][rb + g];
                uint32_t a3 = XsT[kk + q4 + 4][rb + g + 8];
#pragma unroll
                for (int nt = 0; nt < 4; nt++) {
                    asm volatile(
                        "mma.sync.aligned.m16n8k8.row.col.f32.tf32.tf32.f32 "
                        "{%0,%1,%2,%3}, {%4,%5,%6,%7}, {%8,%9}, {%0,%1,%2,%3};"
                        : "+f"(acc[mt][nt][0]), "+f"(acc[mt][nt][1]),
                          "+f"(acc[mt][nt][2]), "+f"(acc[mt][nt][3])
                        : "r"(a0), "r"(a1), "r"(a2), "r"(a3), "r"(b0[nt]), "r"(b1[nt]));
                }
            }
        }
        __syncthreads();
    }

#pragma unroll
    for (int mt = 0; mt < 2; mt++) {
        const int r = bm0 + wm + mt * 16 + g;
#pragma unroll
        for (int nt = 0; nt < 4; nt++) {
            const int c = bn0 + wn + nt * 8 + 2 * q4;
            *(float2*)&g_XW[(size_t)r * HF + c]       = make_float2(acc[mt][nt][0], acc[mt][nt][1]);
            *(float2*)&g_XW[(size_t)(r + 8) * HF + c] = make_float2(acc[mt][nt][2], acc[mt][nt][3]);
        }
    }
}

// ---------------- kernel 1b: transpose + f1/f2h/fmax (fused) ----------------
__global__ void __launch_bounds__(256) transpose_xw(const float* __restrict__ a_src,
                                                    const float* __restrict__ a_dst) {
    __shared__ float ts[64][65];
    __shared__ float as[64], ad[64];
    __shared__ float f2loc[64];
    const int t = threadIdx.x;
    const int hf0 = blockIdx.x * 64;       // == head h * 64
    const int n0  = blockIdx.y * 64;
    const int h   = blockIdx.x;

    if (t < 64) { as[t] = a_src[hf0 + t]; ad[t] = a_dst[hf0 + t]; }
#pragma unroll
    for (int p = 0; p < 4; p++) {
        int e = t + p * 256;
        int node = e >> 4, c4 = e & 15;
        float4 v = *(const float4*)(g_XW + (size_t)(n0 + node) * HF + hf0 + c4 * 4);
        ts[node][c4 * 4 + 0] = v.x;
        ts[node][c4 * 4 + 1] = v.y;
        ts[node][c4 * 4 + 2] = v.z;
        ts[node][c4 * 4 + 3] = v.w;
    }
    __syncthreads();
#pragma unroll
    for (int p = 0; p < 2; p++) {
        int e = t + p * 256;
        int hf = e >> 3, n8 = e & 7;
        uint4 o;
        unsigned* op = (unsigned*)&o;
#pragma unroll
        for (int i = 0; i < 4; i++)
            op[i] = packh2(ts[n8 * 8 + 2 * i][hf], ts[n8 * 8 + 2 * i + 1][hf]);
        *(uint4*)&g_XWTh[(size_t)(hf0 + hf) * N_NODES + n0 + n8 * 8] = o;
    }
    const int node = t >> 2, q = t & 3;
    float s1 = 0.f, s2 = 0.f;
#pragma unroll
    for (int i = 0; i < 16; i++) {
        float x = ts[node][q * 16 + i];
        s1 += x * as[q * 16 + i];
        s2 += x * ad[q * 16 + i];
    }
    s1 += __shfl_xor_sync(0xffffffffu, s1, 1);
    s1 += __shfl_xor_sync(0xffffffffu, s1, 2);
    s2 += __shfl_xor_sync(0xffffffffu, s2, 1);
    s2 += __shfl_xor_sync(0xffffffffu, s2, 2);
    if (q == 0) {
        float f2v = s2 * LOG2E;
        g_f1[h * N_NODES + n0 + node] = s1 * LOG2E;
        g_f2h[h * N_NODES + n0 + node] = __float2half_rn(f2v);
        f2loc[node] = f2v;
    }
    __syncthreads();
    if (t < 32) {
        float m = fmaxf(f2loc[t], f2loc[t + 32]);
#pragma unroll
        for (int o = 16; o > 0; o >>= 1)
            m = fmaxf(m, __shfl_xor_sync(0xffffffffu, m, o));
        if (t == 0) atomicMax(&g_fmax2i[h], enc_f(m));
    }
}

// ---------------- kernel 4: HMMA aggregation, cp.async pipelined ------------
#define KC 128
#define XS_STRIDE 136                 // halves; 272 B row -> ldmatrix conflict-free
#define XS_TILE   17408u              // 64*136*2 bytes
#define XS_DBUF   34816u              // 2 tiles per pipeline slot
#define F2_OFF    69632u              // 2 slots * 512 B
#define AGG_SMEM  70656
#define NIT       (N_NODES / (2 * KC))   // 16

__global__ void __launch_bounds__(256, 2) agg_mma(float* __restrict__ out) {
    extern __shared__ __align__(16) char dsm[];
    const uint32_t sbase = smem_u32(dsm);

    const int t = threadIdx.x;
    const int grp = t >> 7;            // j-group 0/1
    const int tl  = t & 127;
    const int wid = tl >> 5, lane = t & 31;
    const int h  = blockIdx.x & 3;
    const int i0 = (blockIdx.x >> 2) << 6;
    const int g  = lane >> 2;
    const int q4 = lane & 3;
    const int jb = q4 * 2;
    const int r0 = wid * 16 + g;

    const float fm  = dec_f(g_fmax2i[h]);
    const float f1a = g_f1[h * N_NODES + i0 + r0];
    const float f1b = g_f1[h * N_NODES + i0 + r0 + 8];
    const float ma = fmaxf(f1a + fm, 0.2f * (f1a + fm));
    const float mb = fmaxf(f1b + fm, 0.2f * (f1b + fm));
    const __half2 A1 = __half2half2(__float2half_rn(f1a - ma));
    const __half2 A5 = __half2half2(__float2half_rn(0.2f * f1a - ma));
    const __half2 B1 = __half2half2(__float2half_rn(f1b - mb));
    const __half2 B5 = __half2half2(__float2half_rn(0.2f * f1b - mb));
    const __half2 C02 = __half2half2(__float2half_rn(0.2f));

    const __half*    f2hbase = g_f2h + h * N_NODES;
    const unsigned*  apA = g_Apack2 + ((size_t)(i0 + r0) * 32) * 4 + q4;
    const unsigned*  apB = apA + (size_t)8 * 32 * 4;
    const __half*    xwt = g_XWTh + (size_t)h * FDIM * N_NODES;

    const int ldrow = lane & 7, msel = lane >> 3;
    const uint32_t ldBase0 = sbase + grp * XS_TILE
        + (uint32_t)((((msel >> 1) * 8 + ldrow) * XS_STRIDE + (msel & 1) * 8) * 2);

    float acc[8][4];
#pragma unroll
    for (int nt = 0; nt < 8; nt++)
#pragma unroll
        for (int k = 0; k < 4; k++) acc[nt][k] = 0.f;
    float accd[4] = {0.f, 0.f, 0.f, 0.f};
    const unsigned bones = 0x3C003C00u;

    // ---- stage helper: prefetch both tiles of iteration itx into slot itx&1
#define STAGE(itx) do {                                                          \
        const int _d = (itx) & 1;                                                \
        const uint32_t _db = sbase + _d * XS_DBUF;                               \
        _Pragma("unroll")                                                        \
        for (int q = 0; q < 8; q++) {                                            \
            int e = t + q * 256;                                                 \
            int tile = e >> 10, wi = e & 1023;                                   \
            int f = wi >> 4, cc = wi & 15;                                       \
            uint32_t dst = _db + tile * XS_TILE + (uint32_t)((f * XS_STRIDE + cc * 8) * 2); \
            const __half* src = xwt + (size_t)f * N_NODES + (2 * (itx) + tile) * KC + cc * 8; \
            CP_ASYNC16(dst, src);                                                \
        }                                                                        \
        if (t < 32) {                                                            \
            int tile = t >> 4, i4 = t & 15;                                      \
            uint32_t dst = sbase + F2_OFF + _d * 512 + tile * 256 + i4 * 16;     \
            const __half* src = f2hbase + (2 * (itx) + tile) * KC + i4 * 8;      \
            CP_ASYNC16(dst, src);                                                \
        }                                                                        \
        CP_COMMIT();                                                             \
    } while (0)

    STAGE(0);   // prologue

    for (int it = 0; it < NIT; it++) {
        __syncthreads();                         // prior compute done reading slot (it+1)&1
        if (it + 1 < NIT) { STAGE(it + 1); CP_WAIT1(); }
        else              { CP_WAIT0(); }
        __syncthreads();                         // visibility of all threads' copies

        const int d = it & 1;
        const uint32_t ldB = ldBase0 + d * XS_DBUF;
        const __half2* f2p = (const __half2*)(dsm + F2_OFF + d * 512 + grp * 256);

        const int cidx = 2 * it + grp;
        const unsigned wa = apA[cidx * 4];
        const unsigned wb = apB[cidx * 4];

#pragma unroll
        for (int ks = 0; ks < 8; ks++) {
            const int kb = ks * 16;
            const __half2 f01 = f2p[(kb + jb) >> 1];
            const __half2 f89 = f2p[(kb + jb + 8) >> 1];

            const unsigned ra = wa << (7 - ks);
            const unsigned rb = wb << (7 - ks);
            const unsigned mka01 = prmt(ra, 0x9988u);
            const unsigned mka89 = prmt(ra, 0xBBAAu);
            const unsigned mkb01 = prmt(rb, 0x9988u);
            const unsigned mkb89 = prmt(rb, 0xBBAAu);

            __half2 sa01 = __hmax2(__hadd2(A1, f01), __hfma2(C02, f01, A5));
            __half2 sa89 = __hmax2(__hadd2(A1, f89), __hfma2(C02, f89, A5));
            __half2 sb01 = __hmax2(__hadd2(B1, f01), __hfma2(C02, f01, B5));
            __half2 sb89 = __hmax2(__hadd2(B1, f89), __hfma2(C02, f89, B5));
            const unsigned a0 = ex2h2(*(unsigned*)&sa01) & mka01;
            const unsigned a1 = ex2h2(*(unsigned*)&sb01) & mkb01;
            const unsigned a2 = ex2h2(*(unsigned*)&sa89) & mka89;
            const unsigned a3 = ex2h2(*(unsigned*)&sb89) & mkb89;

            asm volatile(
                "mma.sync.aligned.m16n8k16.row.col.f32.f16.f16.f32 "
                "{%0,%1,%2,%3}, {%4,%5,%6,%7}, {%8,%9}, {%0,%1,%2,%3};"
                : "+f"(accd[0]), "+f"(accd[1]), "+f"(accd[2]), "+f"(accd[3])
                : "r"(a0), "r"(a1), "r"(a2), "r"(a3), "r"(bones), "r"(bones));

#pragma unroll
            for (int p = 0; p < 4; p++) {
                uint32_t bb0, bb1, bb2, bb3;
                uint32_t addr = ldB + (uint32_t)((p * 16 * XS_STRIDE + kb) * 2);
                asm volatile("ldmatrix.sync.aligned.m8n8.x4.shared.b16 {%0,%1,%2,%3}, [%4];"
                             : "=r"(bb0), "=r"(bb1), "=r"(bb2), "=r"(bb3) : "r"(addr));
                asm volatile(
                    "mma.sync.aligned.m16n8k16.row.col.f32.f16.f16.f32 "
                    "{%0,%1,%2,%3}, {%4,%5,%6,%7}, {%8,%9}, {%0,%1,%2,%3};"
                    : "+f"(acc[2*p][0]), "+f"(acc[2*p][1]), "+f"(acc[2*p][2]), "+f"(acc[2*p][3])
                    : "r"(a0), "r"(a1), "r"(a2), "r"(a3), "r"(bb0), "r"(bb1));
                asm volatile(
                    "mma.sync.aligned.m16n8k16.row.col.f32.f16.f16.f32 "
                    "{%0,%1,%2,%3}, {%4,%5,%6,%7}, {%8,%9}, {%0,%1,%2,%3};"
                    : "+f"(acc[2*p+1][0]), "+f"(acc[2*p+1][1]), "+f"(acc[2*p+1][2]), "+f"(acc[2*p+1][3])
                    : "r"(a0), "r"(a1), "r"(a2), "r"(a3), "r"(bb2), "r"(bb3));
            }
        }
    }

    // ---- combine group 1 into group 0 via (dead) slot-0 storage -------------
    float* red = (float*)dsm;
    __syncthreads();
    if (grp == 1) {
#pragma unroll
        for (int nt = 0; nt < 8; nt++)
#pragma unroll
            for (int k = 0; k < 4; k++)
                red[(nt * 4 + k) * 128 + tl] = acc[nt][k];
        red[32 * 128 + tl] = accd[0];
        red[33 * 128 + tl] = accd[2];
    }
    __syncthreads();
    if (grp == 0) {
#pragma unroll
        for (int nt = 0; nt < 8; nt++)
#pragma unroll
            for (int k = 0; k < 4; k++)
                acc[nt][k] += red[(nt * 4 + k) * 128 + tl];
        accd[0] += red[32 * 128 + tl];
        accd[2] += red[33 * 128 + tl];

        const float inv0 = 1.f / accd[0];
        const float inv1 = 1.f / accd[2];
        float* ob0 = out + (size_t)(i0 + r0) * HF + h * FDIM + jb;
        float* ob1 = ob0 + (size_t)8 * HF;
#pragma unroll
        for (int nt = 0; nt < 8; nt++) {
            float2 v0, v1;
            v0.x = eluf(acc[nt][0] * inv0);
            v0.y = eluf(acc[nt][1] * inv0);
            v1.x = eluf(acc[nt][2] * inv1);
            v1.y = eluf(acc[nt][3] * inv1);
            *(float2*)(ob0 + nt * 8) = v0;
            *(float2*)(ob1 + nt * 8) = v1;
        }
    }
}

// ---------------- launch ----------------------------------------------------
extern "C" void kernel_launch(void* const* d_in, const int* in_sizes, int n_in,
                              void* d_out, int out_size) {
    const float* X     = (const float*)d_in[0];
    const int*   A     = (const int*)d_in[1];
    const float* W     = (const float*)d_in[2];
    const float* a_src = (const float*)d_in[3];
    const float* a_dst = (const float*)d_in[4];
    float* out = (float*)d_out;

    cudaFuncSetAttribute(agg_mma, cudaFuncAttributeMaxDynamicSharedMemorySize, AGG_SMEM);

    pack_a<<<N_NODES, 128>>>(A);
    dim3 ggrid(HF / 64, N_NODES / 128);
    gemm_xw<<<ggrid, 256>>>(X, W);
    dim3 tgrid(HF / 64, N_NODES / 64);
    transpose_xw<<<tgrid, 256>>>(a_src, a_dst);
    agg_mma<<<(N_NODES / 64) * NHEADS, 256, AGG_SMEM>>>(out);
}

// round 11
// speedup vs baseline: 6.1851x; 1.2119x over previous
#include <cuda_runtime.h>
#include <cuda_fp16.h>
#include <cstdint>

#define N_NODES 4096
#define FIN     512
#define NHEADS  4
#define FDIM    64
#define HF      256
#define LOG2E   1.4426950408889634f

// ---------------- device scratch --------------------------------------------
__device__ float    g_XW[(size_t)N_NODES * HF];        // 4 MB  [node][hf] fp32
__device__ __half   g_XWTh[(size_t)HF * N_NODES];      // 2 MB  [hf][node] fp16
__device__ unsigned g_Apack2[(size_t)N_NODES * 32 * 4];// 2 MB  repacked bitmask
__device__ float    g_f1[NHEADS * N_NODES];
__device__ __half   g_f2h[NHEADS * N_NODES];           // fp16 dst scores
__device__ int      g_fmax2i[NHEADS];

__device__ __forceinline__ int enc_f(float f) {
    int e = __float_as_int(f);
    return (e >= 0) ? e : (e ^ 0x7FFFFFFF);
}
__device__ __forceinline__ float dec_f(int v) {
    return __int_as_float(v >= 0 ? v : (v ^ 0x7FFFFFFF));
}
__device__ __forceinline__ uint32_t f2tf32(float x) {
    uint32_t u;
    asm("cvt.rna.tf32.f32 %0, %1;" : "=r"(u) : "f"(x));
    return u;
}
__device__ __forceinline__ unsigned ex2h2(unsigned x) {
    unsigned r;
    asm("ex2.approx.f16x2 %0, %1;" : "=r"(r) : "r"(x));
    return r;
}
__device__ __forceinline__ unsigned prmt(unsigned a, unsigned sel) {
    unsigned r;
    asm("prmt.b32 %0, %1, %1, %2;" : "=r"(r) : "r"(a), "r"(sel));
    return r;
}
__device__ __forceinline__ unsigned packh2(float a, float b) {
    __half2 h = __floats2half2_rn(a, b);
    return *reinterpret_cast<unsigned*>(&h);
}
__device__ __forceinline__ float eluf(float x) { return x > 0.f ? x : (__expf(x) - 1.f); }
__device__ __forceinline__ uint32_t smem_u32(const void* p) {
    uint32_t a;
    asm("{ .reg .u64 t; cvta.to.shared.u64 t, %1; cvt.u32.u64 %0, t; }" : "=r"(a) : "l"(p));
    return a;
}
#define CP_ASYNC16(dst, src) \
    asm volatile("cp.async.cg.shared.global [%0], [%1], 16;" :: "r"(dst), "l"(src))
#define CP_COMMIT() asm volatile("cp.async.commit_group;" ::: "memory")
#define CP_WAIT1()  asm volatile("cp.async.wait_group 1;" ::: "memory")
#define CP_WAIT0()  asm volatile("cp.async.wait_group 0;" ::: "memory")

// ---------------- kernel 0: repack A -----------------------------------------
__global__ void __launch_bounds__(128) pack_a(const int* __restrict__ A) {
    if (blockIdx.x == 0 && threadIdx.x < NHEADS) g_fmax2i[threadIdx.x] = (int)0x80000000;
    const int row = blockIdx.x;
    const int w = threadIdx.x >> 5, lane = threadIdx.x & 31;
    const int e = lane >> 3, ks = lane & 7;
    const int eoff = (e & 1) + ((e & 2) ? 8 : 0) + ks * 16;
    const int* ar = A + (size_t)row * N_NODES;
#pragma unroll 4
    for (int i = 0; i < 32; i++) {
        int wi = w * 32 + i;
        int c = wi >> 2, q4 = wi & 3;
        int v = ar[c * 128 + 2 * q4 + eoff];
        unsigned b = __ballot_sync(0xffffffffu, v != 0);
        if (lane == 0) g_Apack2[((size_t)row * 32 + c) * 4 + q4] = b;
    }
}

// ---------------- kernel 1: XW = X @ W  via tf32 mma.sync, cp.async ---------
// M=4096, N=256, K=512. CTA: 128x64, BK=32, 8 warps (2n x 4m), warp tile 32x32.
// Raw fp32 tiles staged async; tf32 RNA conversion after LDS.
// X stride 36 words (bank 4g+q4, conflict-free); W stride 72 (bank 8q4+g).
#define GX_STRIDE 36
#define GW_STRIDE 72
#define GX_BUF    18432u          // 128*36*4
#define GW_OFF    36864u          // 2*GX_BUF
#define GW_BUF    9216u           // 32*72*4
#define GEMM_SMEM 55296
#define GNIT      (FIN / 32)      // 16

__global__ void __launch_bounds__(256, 1) gemm_xw(const float* __restrict__ X,
                                                  const float* __restrict__ W) {
    extern __shared__ __align__(16) char gsm[];
    const uint32_t sb = smem_u32(gsm);

    const int t = threadIdx.x, wid = t >> 5, lane = t & 31;
    const int g = lane >> 2, q4 = lane & 3;
    const int bn0 = blockIdx.x * 64;
    const int bm0 = blockIdx.y * 128;
    const int wm = (wid & 3) * 32;
    const int wn = (wid >> 2) * 32;

    float acc[2][4][4];
#pragma unroll
    for (int mt = 0; mt < 2; mt++)
#pragma unroll
        for (int nt = 0; nt < 4; nt++)
#pragma unroll
            for (int k = 0; k < 4; k++) acc[mt][nt][k] = 0.f;

#define GSTAGE(ki) do {                                                        \
        const int _d = (ki) & 1;                                               \
        const int _k0 = (ki) * 32;                                             \
        _Pragma("unroll")                                                      \
        for (int q = 0; q < 4; q++) {       /* X: 128 rows x 32 f = 1024x16B */\
            int e = t + q * 256;                                               \
            int row = e >> 3, c16 = e & 7;                                     \
            uint32_t dst = sb + _d * GX_BUF + (uint32_t)(row * (GX_STRIDE*4) + c16 * 16); \
            const float* src = X + (size_t)(bm0 + row) * FIN + _k0 + c16 * 4;  \
            CP_ASYNC16(dst, src);                                              \
        }                                                                      \
        _Pragma("unroll")                                                      \
        for (int q = 0; q < 2; q++) {       /* W: 32 rows x 64 f = 512x16B  */ \
            int e = t + q * 256;                                               \
            int row = e >> 4, c16 = e & 15;                                    \
            uint32_t dst = sb + GW_OFF + _d * GW_BUF + (uint32_t)(row * (GW_STRIDE*4) + c16 * 16); \
            const float* src = W + (size_t)(_k0 + row) * HF + bn0 + c16 * 4;   \
            CP_ASYNC16(dst, src);                                              \
        }                                                                      \
        CP_COMMIT();                                                           \
    } while (0)

    GSTAGE(0);

    for (int ki = 0; ki < GNIT; ki++) {
        __syncthreads();
        if (ki + 1 < GNIT) { GSTAGE(ki + 1); CP_WAIT1(); }
        else               { CP_WAIT0(); }
        __syncthreads();

        const int d = ki & 1;
        const float* xsp = (const float*)(gsm + d * GX_BUF);
        const float* wsp = (const float*)(gsm + GW_OFF + d * GW_BUF);

#pragma unroll
        for (int ks = 0; ks < 4; ks++) {
            const int kk = ks * 8;
            uint32_t b0[4], b1[4];
#pragma unroll
            for (int nt = 0; nt < 4; nt++) {
                b0[nt] = f2tf32(wsp[(kk + q4) * GW_STRIDE + wn + nt * 8 + g]);
                b1[nt] = f2tf32(wsp[(kk + 4 + q4) * GW_STRIDE + wn + nt * 8 + g]);
            }
#pragma unroll
            for (int mt = 0; mt < 2; mt++) {
                const int rb = wm + mt * 16;
                uint32_t a0 = f2tf32(xsp[(rb + g) * GX_STRIDE + kk + q4]);
                uint32_t a1 = f2tf32(xsp[(rb + g + 8) * GX_STRIDE + kk + q4]);
                uint32_t a2 = f2tf32(xsp[(rb + g) * GX_STRIDE + kk + q4 + 4]);
                uint32_t a3 = f2tf32(xsp[(rb + g + 8) * GX_STRIDE + kk + q4 + 4]);
#pragma unroll
                for (int nt = 0; nt < 4; nt++) {
                    asm volatile(
                        "mma.sync.aligned.m16n8k8.row.col.f32.tf32.tf32.f32 "
                        "{%0,%1,%2,%3}, {%4,%5,%6,%7}, {%8,%9}, {%0,%1,%2,%3};"
                        : "+f"(acc[mt][nt][0]), "+f"(acc[mt][nt][1]),
                          "+f"(acc[mt][nt][2]), "+f"(acc[mt][nt][3])
                        : "r"(a0), "r"(a1), "r"(a2), "r"(a3), "r"(b0[nt]), "r"(b1[nt]));
                }
            }
        }
    }

#pragma unroll
    for (int mt = 0; mt < 2; mt++) {
        const int r = bm0 + wm + mt * 16 + g;
#pragma unroll
        for (int nt = 0; nt < 4; nt++) {
            const int c = bn0 + wn + nt * 8 + 2 * q4;
            *(float2*)&g_XW[(size_t)r * HF + c]       = make_float2(acc[mt][nt][0], acc[mt][nt][1]);
            *(float2*)&g_XW[(size_t)(r + 8) * HF + c] = make_float2(acc[mt][nt][2], acc[mt][nt][3]);
        }
    }
}

// ---------------- kernel 1b: transpose + f1/f2h/fmax (fused) ----------------
__global__ void __launch_bounds__(256) transpose_xw(const float* __restrict__ a_src,
                                                    const float* __restrict__ a_dst) {
    __shared__ float ts[64][65];
    __shared__ float as[64], ad[64];
    __shared__ float f2loc[64];
    const int t = threadIdx.x;
    const int hf0 = blockIdx.x * 64;       // == head h * 64
    const int n0  = blockIdx.y * 64;
    const int h   = blockIdx.x;

    if (t < 64) { as[t] = a_src[hf0 + t]; ad[t] = a_dst[hf0 + t]; }
#pragma unroll
    for (int p = 0; p < 4; p++) {
        int e = t + p * 256;
        int node = e >> 4, c4 = e & 15;
        float4 v = *(const float4*)(g_XW + (size_t)(n0 + node) * HF + hf0 + c4 * 4);
        ts[node][c4 * 4 + 0] = v.x;
        ts[node][c4 * 4 + 1] = v.y;
        ts[node][c4 * 4 + 2] = v.z;
        ts[node][c4 * 4 + 3] = v.w;
    }
    __syncthreads();
#pragma unroll
    for (int p = 0; p < 2; p++) {
        int e = t + p * 256;
        int hf = e >> 3, n8 = e & 7;
        uint4 o;
        unsigned* op = (unsigned*)&o;
#pragma unroll
        for (int i = 0; i < 4; i++)
            op[i] = packh2(ts[n8 * 8 + 2 * i][hf], ts[n8 * 8 + 2 * i + 1][hf]);
        *(uint4*)&g_XWTh[(size_t)(hf0 + hf) * N_NODES + n0 + n8 * 8] = o;
    }
    const int node = t >> 2, q = t & 3;
    float s1 = 0.f, s2 = 0.f;
#pragma unroll
    for (int i = 0; i < 16; i++) {
        float x = ts[node][q * 16 + i];
        s1 += x * as[q * 16 + i];
        s2 += x * ad[q * 16 + i];
    }
    s1 += __shfl_xor_sync(0xffffffffu, s1, 1);
    s1 += __shfl_xor_sync(0xffffffffu, s1, 2);
    s2 += __shfl_xor_sync(0xffffffffu, s2, 1);
    s2 += __shfl_xor_sync(0xffffffffu, s2, 2);
    if (q == 0) {
        float f2v = s2 * LOG2E;
        g_f1[h * N_NODES + n0 + node] = s1 * LOG2E;
        g_f2h[h * N_NODES + n0 + node] = __float2half_rn(f2v);
        f2loc[node] = f2v;
    }
    __syncthreads();
    if (t < 32) {
        float m = fmaxf(f2loc[t], f2loc[t + 32]);
#pragma unroll
        for (int o = 16; o > 0; o >>= 1)
            m = fmaxf(m, __shfl_xor_sync(0xffffffffu, m, o));
        if (t == 0) atomicMax(&g_fmax2i[h], enc_f(m));
    }
}

// ---------------- kernel 4: HMMA aggregation, cp.async pipelined ------------
#define KC 128
#define XS_STRIDE 136                 // halves; 272 B row -> ldmatrix conflict-free
#define XS_TILE   17408u              // 64*136*2 bytes
#define XS_DBUF   34816u              // 2 tiles per pipeline slot
#define F2_OFF    69632u              // 2 slots * 512 B
#define AGG_SMEM  70656
#define NIT       (N_NODES / (2 * KC))   // 16

__global__ void __launch_bounds__(256, 2) agg_mma(float* __restrict__ out) {
    extern __shared__ __align__(16) char dsm[];
    const uint32_t sbase = smem_u32(dsm);

    const int t = threadIdx.x;
    const int grp = t >> 7;            // j-group 0/1
    const int tl  = t & 127;
    const int wid = tl >> 5, lane = t & 31;
    const int h  = blockIdx.x & 3;
    const int i0 = (blockIdx.x >> 2) << 6;
    const int g  = lane >> 2;
    const int q4 = lane & 3;
    const int jb = q4 * 2;
    const int r0 = wid * 16 + g;

    const float fm  = dec_f(g_fmax2i[h]);
    const float f1a = g_f1[h * N_NODES + i0 + r0];
    const float f1b = g_f1[h * N_NODES + i0 + r0 + 8];
    const float ma = fmaxf(f1a + fm, 0.2f * (f1a + fm));
    const float mb = fmaxf(f1b + fm, 0.2f * (f1b + fm));
    const __half2 A1 = __half2half2(__float2half_rn(f1a - ma));
    const __half2 A5 = __half2half2(__float2half_rn(0.2f * f1a - ma));
    const __half2 B1 = __half2half2(__float2half_rn(f1b - mb));
    const __half2 B5 = __half2half2(__float2half_rn(0.2f * f1b - mb));
    const __half2 C02 = __half2half2(__float2half_rn(0.2f));

    const __half*    f2hbase = g_f2h + h * N_NODES;
    const unsigned*  apA = g_Apack2 + ((size_t)(i0 + r0) * 32) * 4 + q4;
    const unsigned*  apB = apA + (size_t)8 * 32 * 4;
    const __half*    xwt = g_XWTh + (size_t)h * FDIM * N_NODES;

    const int ldrow = lane & 7, msel = lane >> 3;
    const uint32_t ldBase0 = sbase + grp * XS_TILE
        + (uint32_t)((((msel >> 1) * 8 + ldrow) * XS_STRIDE + (msel & 1) * 8) * 2);

    float acc[8][4];
#pragma unroll
    for (int nt = 0; nt < 8; nt++)
#pragma unroll
        for (int k = 0; k < 4; k++) acc[nt][k] = 0.f;
    float accd[4] = {0.f, 0.f, 0.f, 0.f};
    const unsigned bones = 0x3C003C00u;

#define STAGE(itx) do {                                                          \
        const int _d = (itx) & 1;                                                \
        const uint32_t _db = sbase + _d * XS_DBUF;                               \
        _Pragma("unroll")                                                        \
        for (int q = 0; q < 8; q++) {                                            \
            int e = t + q * 256;                                                 \
            int tile = e >> 10, wi = e & 1023;                                   \
            int f = wi >> 4, cc = wi & 15;                                       \
            uint32_t dst = _db + tile * XS_TILE + (uint32_t)((f * XS_STRIDE + cc * 8) * 2); \
            const __half* src = xwt + (size_t)f * N_NODES + (2 * (itx) + tile) * KC + cc * 8; \
            CP_ASYNC16(dst, src);                                                \
        }                                                                        \
        if (t < 32) {                                                            \
            int tile = t >> 4, i4 = t & 15;                                      \
            uint32_t dst = sbase + F2_OFF + _d * 512 + tile * 256 + i4 * 16;     \
            const __half* src = f2hbase + (2 * (itx) + tile) * KC + i4 * 8;      \
            CP_ASYNC16(dst, src);                                                \
        }                                                                        \
        CP_COMMIT();                                                             \
    } while (0)

    STAGE(0);   // prologue

    // prefetch iteration-0 mask words
    unsigned wa = apA[grp * 4];
    unsigned wb = apB[grp * 4];

    for (int it = 0; it < NIT; it++) {
        __syncthreads();
        if (it + 1 < NIT) { STAGE(it + 1); CP_WAIT1(); }
        else              { CP_WAIT0(); }
        __syncthreads();

        // prefetch next iteration's mask words (hidden under this iter's compute)
        unsigned wa_n = 0, wb_n = 0;
        if (it + 1 < NIT) {
            wa_n = apA[(2 * (it + 1) + grp) * 4];
            wb_n = apB[(2 * (it + 1) + grp) * 4];
        }

        const int d = it & 1;
        const uint32_t ldB = ldBase0 + d * XS_DBUF;
        const __half2* f2p = (const __half2*)(dsm + F2_OFF + d * 512 + grp * 256);

#pragma unroll
        for (int ks = 0; ks < 8; ks++) {
            const int kb = ks * 16;

            // hoist B-fragment loads: LDSM latency overlaps score math
            uint32_t bbv[16];
#pragma unroll
            for (int p = 0; p < 4; p++) {
                uint32_t addr = ldB + (uint32_t)((p * 16 * XS_STRIDE + kb) * 2);
                asm volatile("ldmatrix.sync.aligned.m8n8.x4.shared.b16 {%0,%1,%2,%3}, [%4];"
                             : "=r"(bbv[4*p]), "=r"(bbv[4*p+1]), "=r"(bbv[4*p+2]), "=r"(bbv[4*p+3])
                             : "r"(addr));
            }

            const __half2 f01 = f2p[(kb + jb) >> 1];
            const __half2 f89 = f2p[(kb + jb + 8) >> 1];

            const unsigned ra = wa << (7 - ks);
            const unsigned rb = wb << (7 - ks);
            const unsigned mka01 = prmt(ra, 0x9988u);
            const unsigned mka89 = prmt(ra, 0xBBAAu);
            const unsigned mkb01 = prmt(rb, 0x9988u);
            const unsigned mkb89 = prmt(rb, 0xBBAAu);

            __half2 sa01 = __hmax2(__hadd2(A1, f01), __hfma2(C02, f01, A5));
            __half2 sa89 = __hmax2(__hadd2(A1, f89), __hfma2(C02, f89, A5));
            __half2 sb01 = __hmax2(__hadd2(B1, f01), __hfma2(C02, f01, B5));
            __half2 sb89 = __hmax2(__hadd2(B1, f89), __hfma2(C02, f89, B5));
            const unsigned a0 = ex2h2(*(unsigned*)&sa01) & mka01;
            const unsigned a1 = ex2h2(*(unsigned*)&sb01) & mkb01;
            const unsigned a2 = ex2h2(*(unsigned*)&sa89) & mka89;
            const unsigned a3 = ex2h2(*(unsigned*)&sb89) & mkb89;

            asm volatile(
                "mma.sync.aligned.m16n8k16.row.col.f32.f16.f16.f32 "
                "{%0,%1,%2,%3}, {%4,%5,%6,%7}, {%8,%9}, {%0,%1,%2,%3};"
                : "+f"(accd[0]), "+f"(accd[1]), "+f"(accd[2]), "+f"(accd[3])
                : "r"(a0), "r"(a1), "r"(a2), "r"(a3), "r"(bones), "r"(bones));

#pragma unroll
            for (int p = 0; p < 4; p++) {
                asm volatile(
                    "mma.sync.aligned.m16n8k16.row.col.f32.f16.f16.f32 "
                    "{%0,%1,%2,%3}, {%4,%5,%6,%7}, {%8,%9}, {%0,%1,%2,%3};"
                    : "+f"(acc[2*p][0]), "+f"(acc[2*p][1]), "+f"(acc[2*p][2]), "+f"(acc[2*p][3])
                    : "r"(a0), "r"(a1), "r"(a2), "r"(a3), "r"(bbv[4*p]), "r"(bbv[4*p+1]));
                asm volatile(
                    "mma.sync.aligned.m16n8k16.row.col.f32.f16.f16.f32 "
                    "{%0,%1,%2,%3}, {%4,%5,%6,%7}, {%8,%9}, {%0,%1,%2,%3};"
                    : "+f"(acc[2*p+1][0]), "+f"(acc[2*p+1][1]), "+f"(acc[2*p+1][2]), "+f"(acc[2*p+1][3])
                    : "r"(a0), "r"(a1), "r"(a2), "r"(a3), "r"(bbv[4*p+2]), "r"(bbv[4*p+3]));
            }
        }

        wa = wa_n;
        wb = wb_n;
    }

    // ---- combine group 1 into group 0 via (dead) slot-0 storage -------------
    float* red = (float*)dsm;
    __syncthreads();
    if (grp == 1) {
#pragma unroll
        for (int nt = 0; nt < 8; nt++)
#pragma unroll
            for (int k = 0; k < 4; k++)
                red[(nt * 4 + k) * 128 + tl] = acc[nt][k];
        red[32 * 128 + tl] = accd[0];
        red[33 * 128 + tl] = accd[2];
    }
    __syncthreads();
    if (grp == 0) {
#pragma unroll
        for (int nt = 0; nt < 8; nt++)
#pragma unroll
            for (int k = 0; k < 4; k++)
                acc[nt][k] += red[(nt * 4 + k) * 128 + tl];
        accd[0] += red[32 * 128 + tl];
        accd[2] += red[33 * 128 + tl];

        const float inv0 = 1.f / accd[0];
        const float inv1 = 1.f / accd[2];
        float* ob0 = out + (size_t)(i0 + r0) * HF + h * FDIM + jb;
        float* ob1 = ob0 + (size_t)8 * HF;
#pragma unroll
        for (int nt = 0; nt < 8; nt++) {
            float2 v0, v1;
            v0.x = eluf(acc[nt][0] * inv0);
            v0.y = eluf(acc[nt][1] * inv0);
            v1.x = eluf(acc[nt][2] * inv1);
            v1.y = eluf(acc[nt][3] * inv1);
            *(float2*)(ob0 + nt * 8) = v0;
            *(float2*)(ob1 + nt * 8) = v1;
        }
    }
}

// ---------------- launch ----------------------------------------------------
extern "C" void kernel_launch(void* const* d_in, const int* in_sizes, int n_in,
                              void* d_out, int out_size) {
    const float* X     = (const float*)d_in[0];
    const int*   A     = (const int*)d_in[1];
    const float* W     = (const float*)d_in[2];
    const float* a_src = (const float*)d_in[3];
    const float* a_dst = (const float*)d_in[4];
    float* out = (float*)d_out;

    cudaFuncSetAttribute(agg_mma, cudaFuncAttributeMaxDynamicSharedMemorySize, AGG_SMEM);
    cudaFuncSetAttribute(gemm_xw, cudaFuncAttributeMaxDynamicSharedMemorySize, GEMM_SMEM);

    pack_a<<<N_NODES, 128>>>(A);
    dim3 ggrid(HF / 64, N_NODES / 128);
    gemm_xw<<<ggrid, 256, GEMM_SMEM>>>(X, W);
    dim3 tgrid(HF / 64, N_NODES / 64);
    transpose_xw<<<tgrid, 256>>>(a_src, a_dst);
    agg_mma<<<(N_NODES / 64) * NHEADS, 256, AGG_SMEM>>>(out);
}

// round 12
// speedup vs baseline: 6.3479x; 1.0263x over previous
#include <cuda_runtime.h>
#include <cuda_fp16.h>
#include <cstdint>

#define N_NODES 4096
#define FIN     512
#define NHEADS  4
#define FDIM    64
#define HF      256
#define LOG2E   1.4426950408889634f

// ---------------- device scratch --------------------------------------------
__device__ __half   g_XWTh[(size_t)HF * N_NODES];      // 2 MB  [hf][node] fp16
__device__ unsigned g_Apack2[(size_t)N_NODES * 32 * 4];// 2 MB  repacked bitmask
__device__ float    g_f1[NHEADS * N_NODES];
__device__ __half   g_f2h[NHEADS * N_NODES];           // fp16 dst scores
__device__ float    g_fmaxp[NHEADS * 32];              // per-(head, node-tile) f2 max

__device__ __forceinline__ uint32_t f2tf32(float x) {
    uint32_t u;
    asm("cvt.rna.tf32.f32 %0, %1;" : "=r"(u) : "f"(x));
    return u;
}
__device__ __forceinline__ unsigned ex2h2(unsigned x) {
    unsigned r;
    asm("ex2.approx.f16x2 %0, %1;" : "=r"(r) : "r"(x));
    return r;
}
__device__ __forceinline__ unsigned prmt(unsigned a, unsigned sel) {
    unsigned r;
    asm("prmt.b32 %0, %1, %1, %2;" : "=r"(r) : "r"(a), "r"(sel));
    return r;
}
__device__ __forceinline__ unsigned packh2(float a, float b) {
    __half2 h = __floats2half2_rn(a, b);
    return *reinterpret_cast<unsigned*>(&h);
}
__device__ __forceinline__ float eluf(float x) { return x > 0.f ? x : (__expf(x) - 1.f); }
__device__ __forceinline__ uint32_t smem_u32(const void* p) {
    uint32_t a;
    asm("{ .reg .u64 t; cvta.to.shared.u64 t, %1; cvt.u32.u64 %0, t; }" : "=r"(a) : "l"(p));
    return a;
}
#define CP_ASYNC16(dst, src) \
    asm volatile("cp.async.cg.shared.global [%0], [%1], 16;" :: "r"(dst), "l"(src))
#define CP_COMMIT() asm volatile("cp.async.commit_group;" ::: "memory")
#define CP_WAIT1()  asm volatile("cp.async.wait_group 1;" ::: "memory")
#define CP_WAIT0()  asm volatile("cp.async.wait_group 0;" ::: "memory")

// ---------------- kernel 1: fused gemm (tf32 mma) + transpose/f + pack ------
// blocks 0..127: gemm role (bx = bid&3 -> head/bn0, by = bid>>2 -> bm0)
// blocks 128..639: pack role (8 rows per block, 1 row per warp)
#define GX_STRIDE 36
#define GW_STRIDE 72
#define GX_BUF    18432u          // 128*36*4
#define GW_OFF    36864u          // 2*GX_BUF
#define GW_BUF    9216u           // 32*72*4
#define GEMM_SMEM 55296
#define GNIT      (FIN / 32)      // 16
// epilogue smem layout (reuses the 55 KB buffer)
#define TS_STRIDE 68
#define AS_OFF    34816u          // 128*68*4
#define AD_OFF    35072u
#define WM_OFF    35328u

__global__ void __launch_bounds__(256, 1) gemm_pack(const float* __restrict__ X,
                                                    const float* __restrict__ W,
                                                    const int*   __restrict__ A,
                                                    const float* __restrict__ a_src,
                                                    const float* __restrict__ a_dst) {
    extern __shared__ __align__(16) char gsm[];
    const int bid = blockIdx.x;
    const int t = threadIdx.x, wid = t >> 5, lane = t & 31;

    if (bid >= 128) {
        // ---------------- pack role ------------------------------------------
        const int row = (bid - 128) * 8 + wid;
        const int e = lane >> 3, ks = lane & 7;
        const int eoff = (e & 1) + ((e & 2) ? 8 : 0) + ks * 16;
        const int* ar = A + (size_t)row * N_NODES;
        unsigned* outp = g_Apack2 + (size_t)row * 128;
#pragma unroll 16
        for (int wi = 0; wi < 128; wi++) {
            int v = ar[(wi >> 2) * 128 + 2 * (wi & 3) + eoff];
            unsigned b = __ballot_sync(0xffffffffu, v != 0);
            if (lane == 0) outp[wi] = b;
        }
        return;
    }

    // ---------------- gemm role ----------------------------------------------
    const uint32_t sb = smem_u32(gsm);
    const int g = lane >> 2, q4 = lane & 3;
    const int bx = bid & 3, by = bid >> 2;
    const int bn0 = bx * 64;            // == head h * 64
    const int bm0 = by * 128;
    const int wm = (wid & 3) * 32;
    const int wn = (wid >> 2) * 32;

    float acc[2][4][4];
#pragma unroll
    for (int mt = 0; mt < 2; mt++)
#pragma unroll
        for (int nt = 0; nt < 4; nt++)
#pragma unroll
            for (int k = 0; k < 4; k++) acc[mt][nt][k] = 0.f;

#define GSTAGE(ki) do {                                                        \
        const int _d = (ki) & 1;                                               \
        const int _k0 = (ki) * 32;                                             \
        _Pragma("unroll")                                                      \
        for (int q = 0; q < 4; q++) {                                          \
            int e2 = t + q * 256;                                              \
            int row = e2 >> 3, c16 = e2 & 7;                                   \
            uint32_t dst = sb + _d * GX_BUF + (uint32_t)(row * (GX_STRIDE*4) + c16 * 16); \
            const float* src = X + (size_t)(bm0 + row) * FIN + _k0 + c16 * 4;  \
            CP_ASYNC16(dst, src);                                              \
        }                                                                      \
        _Pragma("unroll")                                                      \
        for (int q = 0; q < 2; q++) {                                          \
            int e2 = t + q * 256;                                              \
            int row = e2 >> 4, c16 = e2 & 15;                                  \
            uint32_t dst = sb + GW_OFF + _d * GW_BUF + (uint32_t)(row * (GW_STRIDE*4) + c16 * 16); \
            const float* src = W + (size_t)(_k0 + row) * HF + bn0 + c16 * 4;   \
            CP_ASYNC16(dst, src);                                              \
        }                                                                      \
        CP_COMMIT();                                                           \
    } while (0)

    GSTAGE(0);

    for (int ki = 0; ki < GNIT; ki++) {
        __syncthreads();
        if (ki + 1 < GNIT) { GSTAGE(ki + 1); CP_WAIT1(); }
        else               { CP_WAIT0(); }
        __syncthreads();

        const int d = ki & 1;
        const float* xsp = (const float*)(gsm + d * GX_BUF);
        const float* wsp = (const float*)(gsm + GW_OFF + d * GW_BUF);

#pragma unroll
        for (int ks = 0; ks < 4; ks++) {
            const int kk = ks * 8;
            uint32_t b0[4], b1[4];
#pragma unroll
            for (int nt = 0; nt < 4; nt++) {
                b0[nt] = f2tf32(wsp[(kk + q4) * GW_STRIDE + wn + nt * 8 + g]);
                b1[nt] = f2tf32(wsp[(kk + 4 + q4) * GW_STRIDE + wn + nt * 8 + g]);
            }
#pragma unroll
            for (int mt = 0; mt < 2; mt++) {
                const int rb = wm + mt * 16;
                uint32_t a0 = f2tf32(xsp[(rb + g) * GX_STRIDE + kk + q4]);
                uint32_t a1 = f2tf32(xsp[(rb + g + 8) * GX_STRIDE + kk + q4]);
                uint32_t a2 = f2tf32(xsp[(rb + g) * GX_STRIDE + kk + q4 + 4]);
                uint32_t a3 = f2tf32(xsp[(rb + g + 8) * GX_STRIDE + kk + q4 + 4]);
#pragma unroll
                for (int nt = 0; nt < 4; nt++) {
                    asm volatile(
                        "mma.sync.aligned.m16n8k8.row.col.f32.tf32.tf32.f32 "
                        "{%0,%1,%2,%3}, {%4,%5,%6,%7}, {%8,%9}, {%0,%1,%2,%3};"
                        : "+f"(acc[mt][nt][0]), "+f"(acc[mt][nt][1]),
                          "+f"(acc[mt][nt][2]), "+f"(acc[mt][nt][3])
                        : "r"(a0), "r"(a1), "r"(a2), "r"(a3), "r"(b0[nt]), "r"(b1[nt]));
                }
            }
        }
    }

    // ---- fused epilogue: stage tile, write XWTh, compute f1/f2/fmax --------
    __syncthreads();                         // mainloop smem dead; reuse
    float* ts = (float*)gsm;                 // [128 node][TS_STRIDE] (cols 0..63)
    float* as = (float*)(gsm + AS_OFF);
    float* ad = (float*)(gsm + AD_OFF);
    float* wmx = (float*)(gsm + WM_OFF);

    if (t < 64) { as[t] = a_src[bn0 + t]; ad[t] = a_dst[bn0 + t]; }
#pragma unroll
    for (int mt = 0; mt < 2; mt++) {
        const int r = wm + mt * 16 + g;
#pragma unroll
        for (int nt = 0; nt < 4; nt++) {
            const int c = wn + nt * 8 + 2 * q4;
            ts[r * TS_STRIDE + c]           = acc[mt][nt][0];
            ts[r * TS_STRIDE + c + 1]       = acc[mt][nt][1];
            ts[(r + 8) * TS_STRIDE + c]     = acc[mt][nt][2];
            ts[(r + 8) * TS_STRIDE + c + 1] = acc[mt][nt][3];
        }
    }
    __syncthreads();

    // XWTh fp16 transposed, coalesced 16B stores
#pragma unroll
    for (int p = 0; p < 4; p++) {
        int e = t + p * 256;                 // 0..1023
        int hf = e >> 4, ch = e & 15;        // 64 hf x 16 chunks of 8 nodes
        uint4 o;
        unsigned* op = (unsigned*)&o;
#pragma unroll
        for (int i = 0; i < 4; i++)
            op[i] = packh2(ts[(ch * 8 + 2 * i) * TS_STRIDE + hf],
                           ts[(ch * 8 + 2 * i + 1) * TS_STRIDE + hf]);
        *(uint4*)&g_XWTh[(size_t)(bn0 + hf) * N_NODES + bm0 + ch * 8] = o;
    }

    // f1/f2: 2 threads per node, 32 cols each
    const int node = t >> 1, q = t & 1;
    float s1 = 0.f, s2 = 0.f;
#pragma unroll
    for (int i = 0; i < 32; i++) {
        float x = ts[node * TS_STRIDE + q * 32 + i];
        s1 += x * as[q * 32 + i];
        s2 += x * ad[q * 32 + i];
    }
    s1 += __shfl_xor_sync(0xffffffffu, s1, 1);
    s2 += __shfl_xor_sync(0xffffffffu, s2, 1);
    float f2v = s2 * LOG2E;
    if (q == 0) {
        g_f1[bx * N_NODES + bm0 + node] = s1 * LOG2E;
        g_f2h[bx * N_NODES + bm0 + node] = __float2half_rn(f2v);
    }
    // block max of f2v (q==1 lanes hold same value as partner; harmless)
    float m = f2v;
#pragma unroll
    for (int o = 16; o > 0; o >>= 1)
        m = fmaxf(m, __shfl_xor_sync(0xffffffffu, m, o));
    if (lane == 0) wmx[wid] = m;
    __syncthreads();
    if (t == 0) {
        float r = wmx[0];
#pragma unroll
        for (int w = 1; w < 8; w++) r = fmaxf(r, wmx[w]);
        g_fmaxp[bx * 32 + by] = r;
    }
}

// ---------------- kernel 2: HMMA aggregation, cp.async pipelined ------------
#define KC 128
#define XS_STRIDE 136
#define XS_TILE   17408u
#define XS_DBUF   34816u
#define F2_OFF    69632u
#define AGG_SMEM  70656
#define NIT       (N_NODES / (2 * KC))   // 16

__global__ void __launch_bounds__(256, 2) agg_mma(float* __restrict__ out) {
    extern __shared__ __align__(16) char dsm[];
    const uint32_t sbase = smem_u32(dsm);

    const int t = threadIdx.x;
    const int grp = t >> 7;
    const int tl  = t & 127;
    const int wid = tl >> 5, lane = t & 31;
    const int h  = blockIdx.x & 3;
    const int i0 = (blockIdx.x >> 2) << 6;
    const int g  = lane >> 2;
    const int q4 = lane & 3;
    const int jb = q4 * 2;
    const int r0 = wid * 16 + g;

    float fm = g_fmaxp[h * 32];
#pragma unroll 8
    for (int i = 1; i < 32; i++) fm = fmaxf(fm, g_fmaxp[h * 32 + i]);

    const float f1a = g_f1[h * N_NODES + i0 + r0];
    const float f1b = g_f1[h * N_NODES + i0 + r0 + 8];
    const float ma = fmaxf(f1a + fm, 0.2f * (f1a + fm));
    const float mb = fmaxf(f1b + fm, 0.2f * (f1b + fm));
    const __half2 A1 = __half2half2(__float2half_rn(f1a - ma));
    const __half2 A5 = __half2half2(__float2half_rn(0.2f * f1a - ma));
    const __half2 B1 = __half2half2(__float2half_rn(f1b - mb));
    const __half2 B5 = __half2half2(__float2half_rn(0.2f * f1b - mb));
    const __half2 C02 = __half2half2(__float2half_rn(0.2f));

    const __half*    f2hbase = g_f2h + h * N_NODES;
    const unsigned*  apA = g_Apack2 + ((size_t)(i0 + r0) * 32) * 4 + q4;
    const unsigned*  apB = apA + (size_t)8 * 32 * 4;
    const __half*    xwt = g_XWTh + (size_t)h * FDIM * N_NODES;

    const int ldrow = lane & 7, msel = lane >> 3;
    const uint32_t ldBase0 = sbase + grp * XS_TILE
        + (uint32_t)((((msel >> 1) * 8 + ldrow) * XS_STRIDE + (msel & 1) * 8) * 2);

    float acc[8][4];
#pragma unroll
    for (int nt = 0; nt < 8; nt++)
#pragma unroll
        for (int k = 0; k < 4; k++) acc[nt][k] = 0.f;
    float accd[4] = {0.f, 0.f, 0.f, 0.f};
    const unsigned bones = 0x3C003C00u;

#define STAGE(itx) do {                                                          \
        const int _d = (itx) & 1;                                                \
        const uint32_t _db = sbase + _d * XS_DBUF;                               \
        _Pragma("unroll")                                                        \
        for (int q = 0; q < 8; q++) {                                            \
            int e = t + q * 256;                                                 \
            int tile = e >> 10, wi = e & 1023;                                   \
            int f = wi >> 4, cc = wi & 15;                                       \
            uint32_t dst = _db + tile * XS_TILE + (uint32_t)((f * XS_STRIDE + cc * 8) * 2); \
            const __half* src = xwt + (size_t)f * N_NODES + (2 * (itx) + tile) * KC + cc * 8; \
            CP_ASYNC16(dst, src);                                                \
        }                                                                        \
        if (t < 32) {                                                            \
            int tile = t >> 4, i4 = t & 15;                                      \
            uint32_t dst = sbase + F2_OFF + _d * 512 + tile * 256 + i4 * 16;     \
            const __half* src = f2hbase + (2 * (itx) + tile) * KC + i4 * 8;      \
            CP_ASYNC16(dst, src);                                                \
        }                                                                        \
        CP_COMMIT();                                                             \
    } while (0)

    STAGE(0);

    unsigned wa = apA[grp * 4];
    unsigned wb = apB[grp * 4];

    for (int it = 0; it < NIT; it++) {
        __syncthreads();
        if (it + 1 < NIT) { STAGE(it + 1); CP_WAIT1(); }
        else              { CP_WAIT0(); }
        __syncthreads();

        unsigned wa_n = 0, wb_n = 0;
        if (it + 1 < NIT) {
            wa_n = apA[(2 * (it + 1) + grp) * 4];
            wb_n = apB[(2 * (it + 1) + grp) * 4];
        }

        const int d = it & 1;
        const uint32_t ldB = ldBase0 + d * XS_DBUF;
        const __half2* f2p = (const __half2*)(dsm + F2_OFF + d * 512 + grp * 256);

#pragma unroll
        for (int ks = 0; ks < 8; ks++) {
            const int kb = ks * 16;

            uint32_t bbv[16];
#pragma unroll
            for (int p = 0; p < 4; p++) {
                uint32_t addr = ldB + (uint32_t)((p * 16 * XS_STRIDE + kb) * 2);
                asm volatile("ldmatrix.sync.aligned.m8n8.x4.shared.b16 {%0,%1,%2,%3}, [%4];"
                             : "=r"(bbv[4*p]), "=r"(bbv[4*p+1]), "=r"(bbv[4*p+2]), "=r"(bbv[4*p+3])
                             : "r"(addr));
            }

            const __half2 f01 = f2p[(kb + jb) >> 1];
            const __half2 f89 = f2p[(kb + jb + 8) >> 1];

            const unsigned ra = wa << (7 - ks);
            const unsigned rb = wb << (7 - ks);
            const unsigned mka01 = prmt(ra, 0x9988u);
            const unsigned mka89 = prmt(ra, 0xBBAAu);
            const unsigned mkb01 = prmt(rb, 0x9988u);
            const unsigned mkb89 = prmt(rb, 0xBBAAu);

            __half2 sa01 = __hmax2(__hadd2(A1, f01), __hfma2(C02, f01, A5));
            __half2 sa89 = __hmax2(__hadd2(A1, f89), __hfma2(C02, f89, A5));
            __half2 sb01 = __hmax2(__hadd2(B1, f01), __hfma2(C02, f01, B5));
            __half2 sb89 = __hmax2(__hadd2(B1, f89), __hfma2(C02, f89, B5));
            const unsigned a0 = ex2h2(*(unsigned*)&sa01) & mka01;
            const unsigned a1 = ex2h2(*(unsigned*)&sb01) & mkb01;
            const unsigned a2 = ex2h2(*(unsigned*)&sa89) & mka89;
            const unsigned a3 = ex2h2(*(unsigned*)&sb89) & mkb89;

            asm volatile(
                "mma.sync.aligned.m16n8k16.row.col.f32.f16.f16.f32 "
                "{%0,%1,%2,%3}, {%4,%5,%6,%7}, {%8,%9}, {%0,%1,%2,%3};"
                : "+f"(accd[0]), "+f"(accd[1]), "+f"(accd[2]), "+f"(accd[3])
                : "r"(a0), "r"(a1), "r"(a2), "r"(a3), "r"(bones), "r"(bones));

#pragma unroll
            for (int p = 0; p < 4; p++) {
                asm volatile(
                    "mma.sync.aligned.m16n8k16.row.col.f32.f16.f16.f32 "
                    "{%0,%1,%2,%3}, {%4,%5,%6,%7}, {%8,%9}, {%0,%1,%2,%3};"
                    : "+f"(acc[2*p][0]), "+f"(acc[2*p][1]), "+f"(acc[2*p][2]), "+f"(acc[2*p][3])
                    : "r"(a0), "r"(a1), "r"(a2), "r"(a3), "r"(bbv[4*p]), "r"(bbv[4*p+1]));
                asm volatile(
                    "mma.sync.aligned.m16n8k16.row.col.f32.f16.f16.f32 "
                    "{%0,%1,%2,%3}, {%4,%5,%6,%7}, {%8,%9}, {%0,%1,%2,%3};"
                    : "+f"(acc[2*p+1][0]), "+f"(acc[2*p+1][1]), "+f"(acc[2*p+1][2]), "+f"(acc[2*p+1][3])
                    : "r"(a0), "r"(a1), "r"(a2), "r"(a3), "r"(bbv[4*p+2]), "r"(bbv[4*p+3]));
            }
        }

        wa = wa_n;
        wb = wb_n;
    }

    // ---- combine group 1 into group 0 via (dead) slot-0 storage -------------
    float* red = (float*)dsm;
    __syncthreads();
    if (grp == 1) {
#pragma unroll
        for (int nt = 0; nt < 8; nt++)
#pragma unroll
            for (int k = 0; k < 4; k++)
                red[(nt * 4 + k) * 128 + tl] = acc[nt][k];
        red[32 * 128 + tl] = accd[0];
        red[33 * 128 + tl] = accd[2];
    }
    __syncthreads();
    if (grp == 0) {
#pragma unroll
        for (int nt = 0; nt < 8; nt++)
#pragma unroll
            for (int k = 0; k < 4; k++)
                acc[nt][k] += red[(nt * 4 + k) * 128 + tl];
        accd[0] += red[32 * 128 + tl];
        accd[2] += red[33 * 128 + tl];

        const float inv0 = 1.f / accd[0];
        const float inv1 = 1.f / accd[2];
        float* ob0 = out + (size_t)(i0 + r0) * HF + h * FDIM + jb;
        float* ob1 = ob0 + (size_t)8 * HF;
#pragma unroll
        for (int nt = 0; nt < 8; nt++) {
            float2 v0, v1;
            v0.x = eluf(acc[nt][0] * inv0);
            v0.y = eluf(acc[nt][1] * inv0);
            v1.x = eluf(acc[nt][2] * inv1);
            v1.y = eluf(acc[nt][3] * inv1);
            *(float2*)(ob0 + nt * 8) = v0;
            *(float2*)(ob1 + nt * 8) = v1;
        }
    }
}

// ---------------- launch ----------------------------------------------------
extern "C" void kernel_launch(void* const* d_in, const int* in_sizes, int n_in,
                              void* d_out, int out_size) {
    const float* X     = (const float*)d_in[0];
    const int*   A     = (const int*)d_in[1];
    const float* W     = (const float*)d_in[2];
    const float* a_src = (const float*)d_in[3];
    const float* a_dst = (const float*)d_in[4];
    float* out = (float*)d_out;

    cudaFuncSetAttribute(gemm_pack, cudaFuncAttributeMaxDynamicSharedMemorySize, GEMM_SMEM);
    cudaFuncSetAttribute(agg_mma,  cudaFuncAttributeMaxDynamicSharedMemorySize, AGG_SMEM);

    gemm_pack<<<128 + N_NODES / 8, 256, GEMM_SMEM>>>(X, W, A, a_src, a_dst);
    agg_mma<<<(N_NODES / 64) * NHEADS, 256, AGG_SMEM>>>(out);
}